// round 4
// baseline (speedup 1.0000x reference)
#include <cuda_runtime.h>

#define NQ      12
#define DIM     (1 << NQ)      // 4096 amplitudes
#define NPAIR   (DIM / 2)      // 2048 pairs per 1-qubit gate
#define NT      256            // threads per CTA
#define NWARP   (NT / 32)
#define LAYERS  4
#define NENC    4
#define MAXB    1024

// Per-(encoder, sample, qubit) <Z> results. Static device scratch (no allocs).
__device__ float g_branch[NENC * MAXB * NQ];

// ---------------- complex helpers ----------------
__device__ __forceinline__ float2 cmul(float2 a, float2 b) {
    return make_float2(fmaf(a.x, b.x, -a.y * b.y), fmaf(a.x, b.y, a.y * b.x));
}
__device__ __forceinline__ float2 cadd(float2 a, float2 b) {
    return make_float2(a.x + b.x, a.y + b.y);
}

struct M2 { float2 m00, m01, m10, m11; };

__device__ __forceinline__ M2 mmul(const M2& A, const M2& B) {
    M2 C;
    C.m00 = cadd(cmul(A.m00, B.m00), cmul(A.m01, B.m10));
    C.m01 = cadd(cmul(A.m00, B.m01), cmul(A.m01, B.m11));
    C.m10 = cadd(cmul(A.m10, B.m00), cmul(A.m11, B.m10));
    C.m11 = cadd(cmul(A.m10, B.m01), cmul(A.m11, B.m11));
    return C;
}

__device__ __forceinline__ M2 rx_m(float t) {
    float s, c; sincosf(0.5f * t, &s, &c);
    M2 M;
    M.m00 = make_float2(c, 0.f);  M.m01 = make_float2(0.f, -s);
    M.m10 = make_float2(0.f, -s); M.m11 = make_float2(c, 0.f);
    return M;
}
__device__ __forceinline__ M2 ry_m(float t) {
    float s, c; sincosf(0.5f * t, &s, &c);
    M2 M;
    M.m00 = make_float2(c, 0.f);  M.m01 = make_float2(-s, 0.f);
    M.m10 = make_float2(s, 0.f);  M.m11 = make_float2(c, 0.f);
    return M;
}
__device__ __forceinline__ M2 rz_m(float t) {
    float s, c; sincosf(0.5f * t, &s, &c);
    M2 M;
    M.m00 = make_float2(c, -s);   M.m01 = make_float2(0.f, 0.f);
    M.m10 = make_float2(0.f, 0.f); M.m11 = make_float2(c, s);
    return M;
}

// Apply a 2x2 gate on bit position p (p = 11 - qubit_index, big-endian wires).
__device__ __forceinline__ void apply1(float2* st, int p, const M2 U, int tid) {
    const int lomask = (1 << p) - 1;
    #pragma unroll
    for (int j = tid; j < NPAIR; j += NT) {
        int i0 = ((j >> p) << (p + 1)) | (j & lomask);
        int i1 = i0 | (1 << p);
        float2 a = st[i0], b = st[i1];
        st[i0] = cadd(cmul(U.m00, a), cmul(U.m01, b));
        st[i1] = cadd(cmul(U.m10, a), cmul(U.m11, b));
    }
    __syncthreads();
}

// CNOT with control at bit pc, target at bit pc-1 (adjacent wires q, q+1).
__device__ __forceinline__ void apply_cnot(float2* st, int pc, int tid) {
    const int pt = pc - 1;
    const int lomask = (1 << pt) - 1;
    #pragma unroll
    for (int j = tid; j < DIM / 4; j += NT) {
        int i = ((j >> pt) << (pt + 2)) | (1 << pc) | (j & lomask);  // ctrl=1, tgt=0
        int i2 = i | (1 << pt);
        float2 t = st[i]; st[i] = st[i2]; st[i2] = t;
    }
    __syncthreads();
}

__global__ __launch_bounds__(NT)
void vqc_kernel(const float* __restrict__ features,
                const float* __restrict__ theta,
                int B)
{
    __shared__ float2 st[DIM];
    __shared__ float red[NWARP * NQ];

    const int b   = blockIdx.x;
    const int e   = blockIdx.y;            // 0:rx 1:ry 2:h+rx 3:h+ry
    const int tid = threadIdx.x;

    // |0...0>
    for (int i = tid; i < DIM; i += NT) st[i] = make_float2(0.f, 0.f);
    if (tid == 0) st[0] = make_float2(1.f, 0.f);
    __syncthreads();

    const bool use_h  = (e >= 2);
    const bool use_ry = (e & 1);

    // ---- encoding: (H?) then RX/RY(features[b,q]) — fused into one sweep ----
    for (int q = 0; q < NQ; q++) {
        float f = features[b * NQ + q];
        M2 R = use_ry ? ry_m(f) : rx_m(f);
        if (use_h) {
            const float r = 0.7071067811865476f;
            M2 H;
            H.m00 = make_float2(r, 0.f);  H.m01 = make_float2(r, 0.f);
            H.m10 = make_float2(r, 0.f);  H.m11 = make_float2(-r, 0.f);
            R = mmul(R, H);               // state' = R * (H * state)
        }
        apply1(st, NQ - 1 - q, R, tid);
    }

    // ---- variational layers: fused RZ*RY*RX per qubit, then CNOT ladder ----
    for (int l = 0; l < LAYERS; l++) {
        for (int q = 0; q < NQ; q++) {
            const float* th = theta + (l * NQ + q) * 3;
            M2 M = mmul(rz_m(th[2]), mmul(ry_m(th[1]), rx_m(th[0])));
            apply1(st, NQ - 1 - q, M, tid);
        }
        for (int q = 0; q < NQ - 1; q += 2) apply_cnot(st, NQ - 1 - q, tid);
        for (int q = 1; q < NQ - 1; q += 2) apply_cnot(st, NQ - 1 - q, tid);
    }

    // ---- <Z_q> for all 12 qubits ----
    float ez[NQ];
    #pragma unroll
    for (int q = 0; q < NQ; q++) ez[q] = 0.f;

    for (int i = tid; i < DIM; i += NT) {
        float2 a = st[i];
        float p = fmaf(a.x, a.x, a.y * a.y);
        #pragma unroll
        for (int q = 0; q < NQ; q++)
            ez[q] += ((i >> (NQ - 1 - q)) & 1) ? -p : p;
    }

    #pragma unroll
    for (int q = 0; q < NQ; q++)
        #pragma unroll
        for (int o = 16; o > 0; o >>= 1)
            ez[q] += __shfl_xor_sync(0xffffffffu, ez[q], o);

    const int warp = tid >> 5, lane = tid & 31;
    if (lane == 0) {
        #pragma unroll
        for (int q = 0; q < NQ; q++) red[warp * NQ + q] = ez[q];
    }
    __syncthreads();
    if (tid < NQ) {
        float s = 0.f;
        #pragma unroll
        for (int w = 0; w < NWARP; w++) s += red[w * NQ + tid];
        g_branch[(e * B + b) * NQ + tid] = s;
    }
}

__global__ void reduce_kernel(const float* __restrict__ alpha,
                              float* __restrict__ out, int B)
{
    int idx = blockIdx.x * blockDim.x + threadIdx.x;
    if (idx >= B * NQ) return;
    float a0 = alpha[0], a1 = alpha[1], a2 = alpha[2], a3 = alpha[3];
    float m  = fmaxf(fmaxf(a0, a1), fmaxf(a2, a3));
    float w0 = expf(a0 - m), w1 = expf(a1 - m), w2 = expf(a2 - m), w3 = expf(a3 - m);
    float inv = 1.f / (w0 + w1 + w2 + w3);
    int stride = B * NQ;
    float y = w0 * g_branch[idx]
            + w1 * g_branch[stride + idx]
            + w2 * g_branch[2 * stride + idx]
            + w3 * g_branch[3 * stride + idx];
    out[idx] = y * inv;
}

extern "C" void kernel_launch(void* const* d_in, const int* in_sizes, int n_in,
                              void* d_out, int out_size)
{
    const float* features = (const float*)d_in[0];   // (B, 12)
    const float* theta    = (const float*)d_in[1];   // (4, 12, 3)
    const float* alpha    = (const float*)d_in[2];   // (4,)
    float* out = (float*)d_out;                      // (B, 12)

    int B = in_sizes[0] / NQ;
    if (B > MAXB) B = MAXB;

    dim3 grid(B, NENC);
    vqc_kernel<<<grid, NT>>>(features, theta, B);

    int n = B * NQ;
    reduce_kernel<<<(n + 255) / 256, 256>>>(alpha, out, B);
}

// round 6
// speedup vs baseline: 1.7528x; 1.7528x over previous
#include <cuda_runtime.h>

#define NQ      12
#define DIM     4096
#define NT      256
#define NWARP   8
#define LAYERS  4
#define NENC    4
#define MAXB    1024

// ---------------- static device scratch (no allocations) ----------------
__device__ float  g_branch[NENC * MAXB * NQ];
// fused gate matrices, 2 x float4 each: [m00.x m00.y m01.x m01.y][m10 m11]
__device__ float4 g_vm[LAYERS * NQ * 2];                 // variational (theta)
__device__ float4 g_em[NENC * MAXB * NQ * 2];            // encoding (features)

// ---------------- complex helpers ----------------
__device__ __forceinline__ float2 cmul(float2 a, float2 b) {
    return make_float2(fmaf(a.x, b.x, -a.y * b.y), fmaf(a.x, b.y, a.y * b.x));
}
__device__ __forceinline__ float2 cadd(float2 a, float2 b) {
    return make_float2(a.x + b.x, a.y + b.y);
}

struct M2 { float2 m00, m01, m10, m11; };

__device__ __forceinline__ M2 mmul(const M2& A, const M2& B) {
    M2 C;
    C.m00 = cadd(cmul(A.m00, B.m00), cmul(A.m01, B.m10));
    C.m01 = cadd(cmul(A.m00, B.m01), cmul(A.m01, B.m11));
    C.m10 = cadd(cmul(A.m10, B.m00), cmul(A.m11, B.m10));
    C.m11 = cadd(cmul(A.m10, B.m01), cmul(A.m11, B.m11));
    return C;
}
__device__ __forceinline__ M2 rx_m(float t) {
    float s, c; sincosf(0.5f * t, &s, &c);
    M2 M; M.m00 = {c, 0.f}; M.m01 = {0.f, -s}; M.m10 = {0.f, -s}; M.m11 = {c, 0.f};
    return M;
}
__device__ __forceinline__ M2 ry_m(float t) {
    float s, c; sincosf(0.5f * t, &s, &c);
    M2 M; M.m00 = {c, 0.f}; M.m01 = {-s, 0.f}; M.m10 = {s, 0.f}; M.m11 = {c, 0.f};
    return M;
}
__device__ __forceinline__ M2 rz_m(float t) {
    float s, c; sincosf(0.5f * t, &s, &c);
    M2 M; M.m00 = {c, -s}; M.m01 = {0.f, 0.f}; M.m10 = {0.f, 0.f}; M.m11 = {c, s};
    return M;
}
__device__ __forceinline__ void storeM(float4* dst, const M2& M) {
    dst[0] = make_float4(M.m00.x, M.m00.y, M.m01.x, M.m01.y);
    dst[1] = make_float4(M.m10.x, M.m10.y, M.m11.x, M.m11.y);
}
__device__ __forceinline__ M2 ldM(const float4* p) {
    float4 a = p[0], b = p[1];
    M2 M; M.m00 = {a.x, a.y}; M.m01 = {a.z, a.w}; M.m10 = {b.x, b.y}; M.m11 = {b.z, b.w};
    return M;
}

// ---------------- prep kernels: precompute fused matrices ----------------
__global__ void prep_var_kernel(const float* __restrict__ theta) {
    int idx = blockIdx.x * blockDim.x + threadIdx.x;        // l*NQ + q
    if (idx >= LAYERS * NQ) return;
    const float* th = theta + idx * 3;
    M2 M = mmul(rz_m(th[2]), mmul(ry_m(th[1]), rx_m(th[0])));
    storeM(&g_vm[idx * 2], M);
}

__global__ void prep_enc_kernel(const float* __restrict__ features, int B) {
    int idx = blockIdx.x * blockDim.x + threadIdx.x;        // e*B*NQ + b*NQ + q
    if (idx >= NENC * B * NQ) return;
    int q = idx % NQ;
    int b = (idx / NQ) % B;
    int e = idx / (B * NQ);
    float f = features[b * NQ + q];
    M2 R = (e & 1) ? ry_m(f) : rx_m(f);
    if (e >= 2) {
        const float r = 0.7071067811865476f;
        M2 H; H.m00 = {r, 0.f}; H.m01 = {r, 0.f}; H.m10 = {r, 0.f}; H.m11 = {-r, 0.f};
        R = mmul(R, H);                                     // state' = R * (H * state)
    }
    storeM(&g_em[idx * 2], R);
}

// ---------------- register-resident gate primitives ----------------
// Amplitude index: i = (tid << 4) | k. Bits 0-3 = k (registers),
// bits 4-8 = lane, bits 9-11 = warp id.

template<int P>
__device__ __forceinline__ void gate_local(float2 s[16], const M2 M) {
    #pragma unroll
    for (int k = 0; k < 16; k++) {
        if (!(k & (1 << P))) {
            const int k1 = k | (1 << P);
            float2 a = s[k], b = s[k1];
            s[k]  = cadd(cmul(M.m00, a), cmul(M.m01, b));
            s[k1] = cadd(cmul(M.m10, a), cmul(M.m11, b));
        }
    }
}

__device__ __forceinline__ void gate_lane(float2 s[16], const M2 M, int mask, int lane) {
    const bool hi = lane & mask;
    const float2 ua = hi ? M.m10 : M.m00;     // coeff of bit=0 amplitude
    const float2 ub = hi ? M.m11 : M.m01;     // coeff of bit=1 amplitude
    #pragma unroll
    for (int k = 0; k < 16; k++) {
        float2 o;
        o.x = __shfl_xor_sync(0xffffffffu, s[k].x, mask);
        o.y = __shfl_xor_sync(0xffffffffu, s[k].y, mask);
        float2 a0 = hi ? o : s[k];
        float2 a1 = hi ? s[k] : o;
        s[k] = cadd(cmul(ua, a0), cmul(ub, a1));
    }
}

__device__ __forceinline__ void gate_warp(float2 s[16], const M2 M, int wmask,
                                          float4* xch, int tid, int w) {
    #pragma unroll
    for (int j = 0; j < 8; j++)
        xch[j * NT + tid] = make_float4(s[2*j].x, s[2*j].y, s[2*j+1].x, s[2*j+1].y);
    __syncthreads();
    const bool hi = w & wmask;
    const float2 ua = hi ? M.m10 : M.m00;
    const float2 ub = hi ? M.m11 : M.m01;
    const int ptid = tid ^ (wmask << 5);
    #pragma unroll
    for (int j = 0; j < 8; j++) {
        float4 v = xch[j * NT + ptid];
        float2 o0 = {v.x, v.y}, o1 = {v.z, v.w};
        float2 a0 = hi ? o0 : s[2*j];
        float2 a1 = hi ? s[2*j] : o0;
        s[2*j] = cadd(cmul(ua, a0), cmul(ub, a1));
        a0 = hi ? o1 : s[2*j+1];
        a1 = hi ? s[2*j+1] : o1;
        s[2*j+1] = cadd(cmul(ua, a0), cmul(ub, a1));
    }
    __syncthreads();
}

// 12-gate commuting sweep, one matrix per qubit q=0..11 (bit 11-q)
__device__ __forceinline__ void sweep12(const float4* mats, float2 s[16],
                                        float4* xch, int tid, int lane, int w) {
    gate_warp(s, ldM(mats + 0),  4, xch, tid, w);   // q=0,  bit 11
    gate_warp(s, ldM(mats + 2),  2, xch, tid, w);   // q=1,  bit 10
    gate_warp(s, ldM(mats + 4),  1, xch, tid, w);   // q=2,  bit 9
    gate_lane(s, ldM(mats + 6),  16, lane);         // q=3,  bit 8
    gate_lane(s, ldM(mats + 8),   8, lane);         // q=4,  bit 7
    gate_lane(s, ldM(mats + 10),  4, lane);         // q=5,  bit 6
    gate_lane(s, ldM(mats + 12),  2, lane);         // q=6,  bit 5
    gate_lane(s, ldM(mats + 14),  1, lane);         // q=7,  bit 4
    gate_local<3>(s, ldM(mats + 16));               // q=8,  bit 3
    gate_local<2>(s, ldM(mats + 18));               // q=9,  bit 2
    gate_local<1>(s, ldM(mats + 20));               // q=10, bit 1
    gate_local<0>(s, ldM(mats + 22));               // q=11, bit 0
}

// ---------------- CNOT primitives (control = higher bit, target = ctrl-1) --
template<int PC, int PT>
__device__ __forceinline__ void cnot_local(float2 s[16]) {
    #pragma unroll
    for (int k = 0; k < 16; k++) {
        if ((k & (1 << PC)) && !(k & (1 << PT))) {
            const int k1 = k | (1 << PT);
            float2 t = s[k]; s[k] = s[k1]; s[k1] = t;
        }
    }
}

__device__ __forceinline__ void cnot_lane(float2 s[16], int cmask, int tmask, int lane) {
    const bool c = lane & cmask;
    #pragma unroll
    for (int k = 0; k < 16; k++) {
        float x = __shfl_xor_sync(0xffffffffu, s[k].x, tmask);
        float y = __shfl_xor_sync(0xffffffffu, s[k].y, tmask);
        if (c) { s[k].x = x; s[k].y = y; }
    }
}

// ctrl = lane bit 0 (bit 4), tgt = local bit 3: predicated register swap
__device__ __forceinline__ void cnot_lane_local(float2 s[16], int lane) {
    if (lane & 1) {
        #pragma unroll
        for (int k = 0; k < 8; k++) { float2 t = s[k]; s[k] = s[k + 8]; s[k + 8] = t; }
    }
}

// ctrl = warp bit 0 (bit 9), tgt = lane bit 4 (bit 8): warp-uniform shfl swap
__device__ __forceinline__ void cnot_w_lane(float2 s[16], int w) {
    if (w & 1) {
        #pragma unroll
        for (int k = 0; k < 16; k++) {
            s[k].x = __shfl_xor_sync(0xffffffffu, s[k].x, 16);
            s[k].y = __shfl_xor_sync(0xffffffffu, s[k].y, 16);
        }
    }
}

// ctrl, tgt both warp bits: smem exchange between warp pairs with ctrl=1
__device__ __forceinline__ void cnot_warp(float2 s[16], int cmask, int tmask,
                                          float4* xch, int tid, int w) {
    const bool act = w & cmask;
    if (act) {
        #pragma unroll
        for (int j = 0; j < 8; j++)
            xch[j * NT + tid] = make_float4(s[2*j].x, s[2*j].y, s[2*j+1].x, s[2*j+1].y);
    }
    __syncthreads();
    if (act) {
        const int ptid = tid ^ (tmask << 5);
        #pragma unroll
        for (int j = 0; j < 8; j++) {
            float4 v = xch[j * NT + ptid];
            s[2*j]   = make_float2(v.x, v.y);
            s[2*j+1] = make_float2(v.z, v.w);
        }
    }
    __syncthreads();
}

// ---------------- main kernel ----------------
__global__ __launch_bounds__(NT, 2)
void vqc_reg_kernel(int B)
{
    __shared__ float4 xch[8 * NT];          // 32 KB exchange buffer
    __shared__ float  red[NWARP * NQ];

    const int b    = blockIdx.x;
    const int e    = blockIdx.y;
    const int tid  = threadIdx.x;
    const int lane = tid & 31;
    const int w    = tid >> 5;

    // |0...0>
    float2 s[16];
    #pragma unroll
    for (int k = 0; k < 16; k++) s[k] = make_float2(0.f, 0.f);
    if (tid == 0) s[0] = make_float2(1.f, 0.f);

    // ---- encoding sweep (H fused into rotation, precomputed) ----
    sweep12(g_em + ((e * B + b) * NQ) * 2, s, xch, tid, lane, w);

    // ---- variational layers ----
    #pragma unroll 1
    for (int l = 0; l < LAYERS; l++) {
        sweep12(g_vm + (l * NQ) * 2, s, xch, tid, lane, w);
        // even ladder: q = 0,2,4,6,8,10 -> bit pairs
        //   (11,10)(9,8)(7,6)(5,4)(3,2)(1,0)   <- SIX CNOTs (q=10 was missing in R4)
        cnot_warp(s, 4, 2, xch, tid, w);     // (11,10)
        cnot_w_lane(s, w);                   // (9,8)
        cnot_lane(s, 8, 4, lane);            // (7,6)
        cnot_lane(s, 2, 1, lane);            // (5,4)
        cnot_local<3, 2>(s);                 // (3,2)
        cnot_local<1, 0>(s);                 // (1,0)  <- FIX
        // odd ladder: q = 1,3,5,7,9 -> (10,9)(8,7)(6,5)(4,3)(2,1)
        cnot_warp(s, 2, 1, xch, tid, w);     // (10,9)
        cnot_lane(s, 16, 8, lane);           // (8,7)
        cnot_lane(s, 4, 2, lane);            // (6,5)
        cnot_lane_local(s, lane);            // (4,3)
        cnot_local<2, 1>(s);                 // (2,1)
    }

    // ---- <Z_q> for all 12 qubits ----
    float t[16], tot = 0.f;
    #pragma unroll
    for (int k = 0; k < 16; k++) {
        t[k] = fmaf(s[k].x, s[k].x, s[k].y * s[k].y);
        tot += t[k];
    }
    float ez[NQ];
    #pragma unroll
    for (int q = 0; q < 8; q++)          // bits 11..4: sign fixed per thread
        ez[q] = ((tid >> (7 - q)) & 1) ? -tot : tot;
    #pragma unroll
    for (int q = 8; q < 12; q++) {       // bits 3..0: sign varies over k
        const int P = 11 - q;
        float a = 0.f;
        #pragma unroll
        for (int k = 0; k < 16; k++) a += ((k >> P) & 1) ? -t[k] : t[k];
        ez[q] = a;
    }

    #pragma unroll
    for (int q = 0; q < NQ; q++)
        #pragma unroll
        for (int o = 16; o > 0; o >>= 1)
            ez[q] += __shfl_xor_sync(0xffffffffu, ez[q], o);

    if (lane == 0) {
        #pragma unroll
        for (int q = 0; q < NQ; q++) red[w * NQ + q] = ez[q];
    }
    __syncthreads();
    if (tid < NQ) {
        float acc = 0.f;
        #pragma unroll
        for (int j = 0; j < NWARP; j++) acc += red[j * NQ + tid];
        g_branch[(e * B + b) * NQ + tid] = acc;
    }
}

// ---------------- softmax(alpha)-weighted branch mix ----------------
__global__ void reduce_kernel(const float* __restrict__ alpha,
                              float* __restrict__ out, int B)
{
    int idx = blockIdx.x * blockDim.x + threadIdx.x;
    if (idx >= B * NQ) return;
    float a0 = alpha[0], a1 = alpha[1], a2 = alpha[2], a3 = alpha[3];
    float m  = fmaxf(fmaxf(a0, a1), fmaxf(a2, a3));
    float w0 = expf(a0 - m), w1 = expf(a1 - m), w2 = expf(a2 - m), w3 = expf(a3 - m);
    float inv = 1.f / (w0 + w1 + w2 + w3);
    int stride = B * NQ;
    float y = w0 * g_branch[idx]
            + w1 * g_branch[stride + idx]
            + w2 * g_branch[2 * stride + idx]
            + w3 * g_branch[3 * stride + idx];
    out[idx] = y * inv;
}

extern "C" void kernel_launch(void* const* d_in, const int* in_sizes, int n_in,
                              void* d_out, int out_size)
{
    const float* features = (const float*)d_in[0];   // (B, 12)
    const float* theta    = (const float*)d_in[1];   // (4, 12, 3)
    const float* alpha    = (const float*)d_in[2];   // (4,)
    float* out = (float*)d_out;                      // (B, 12)

    int B = in_sizes[0] / NQ;
    if (B > MAXB) B = MAXB;

    prep_var_kernel<<<1, 64>>>(theta);
    int nenc = NENC * B * NQ;
    prep_enc_kernel<<<(nenc + 255) / 256, 256>>>(features, B);

    dim3 grid(B, NENC);
    vqc_reg_kernel<<<grid, NT>>>(B);

    int n = B * NQ;
    reduce_kernel<<<(n + 255) / 256, 256>>>(alpha, out, B);
}

// round 7
// speedup vs baseline: 2.0653x; 1.1783x over previous
#include <cuda_runtime.h>

#define NQ      12
#define NT      256
#define NWARP   8
#define LAYERS  4
#define NENC    4
#define MAXB    1024

typedef unsigned long long u64;

// ---------------- static device scratch (no allocations) ----------------
__device__ float  g_branch[NENC * MAXB * NQ];
// variational gates, packed-broadcast form: 4 float4 per gate
//   f4[m] = (re, re, -im, im) for m in {m00, m01, m10, m11}
__device__ float4 g_vm[LAYERS * NQ * 4];
// encoding: first column of R(·H) per (e,b,q): (c0.x, c0.y, c1.x, c1.y)
__device__ float4 g_em[NENC * MAXB * NQ];

// ---------------- scalar complex helpers (prep + encoding) ----------------
__device__ __forceinline__ float2 cmul(float2 a, float2 b) {
    return make_float2(fmaf(a.x, b.x, -a.y * b.y), fmaf(a.x, b.y, a.y * b.x));
}
__device__ __forceinline__ float2 cadd(float2 a, float2 b) {
    return make_float2(a.x + b.x, a.y + b.y);
}
struct M2 { float2 m00, m01, m10, m11; };
__device__ __forceinline__ M2 mmul(const M2& A, const M2& B) {
    M2 C;
    C.m00 = cadd(cmul(A.m00, B.m00), cmul(A.m01, B.m10));
    C.m01 = cadd(cmul(A.m00, B.m01), cmul(A.m01, B.m11));
    C.m10 = cadd(cmul(A.m10, B.m00), cmul(A.m11, B.m10));
    C.m11 = cadd(cmul(A.m10, B.m01), cmul(A.m11, B.m11));
    return C;
}
__device__ __forceinline__ M2 rx_m(float t) {
    float s, c; sincosf(0.5f * t, &s, &c);
    M2 M; M.m00 = {c, 0.f}; M.m01 = {0.f, -s}; M.m10 = {0.f, -s}; M.m11 = {c, 0.f};
    return M;
}
__device__ __forceinline__ M2 ry_m(float t) {
    float s, c; sincosf(0.5f * t, &s, &c);
    M2 M; M.m00 = {c, 0.f}; M.m01 = {-s, 0.f}; M.m10 = {s, 0.f}; M.m11 = {c, 0.f};
    return M;
}
__device__ __forceinline__ M2 rz_m(float t) {
    float s, c; sincosf(0.5f * t, &s, &c);
    M2 M; M.m00 = {c, -s}; M.m01 = {0.f, 0.f}; M.m10 = {0.f, 0.f}; M.m11 = {c, s};
    return M;
}

// ---------------- packed f32x2 primitives ----------------
__device__ __forceinline__ u64 pk2(float x, float y) {
    u64 r; asm("mov.b64 %0, {%1, %2};" : "=l"(r) : "f"(x), "f"(y)); return r;
}
__device__ __forceinline__ void upk2(u64 v, float& x, float& y) {
    asm("mov.b64 {%0, %1}, %2;" : "=f"(x), "=f"(y) : "l"(v));
}
__device__ __forceinline__ u64 pswap(u64 v) {           // (x,y) -> (y,x)
    float x, y; upk2(v, x, y); return pk2(y, x);
}
__device__ __forceinline__ u64 pmul(u64 a, u64 b) {
    u64 r; asm("mul.rn.f32x2 %0, %1, %2;" : "=l"(r) : "l"(a), "l"(b)); return r;
}
__device__ __forceinline__ u64 pfma(u64 a, u64 b, u64 c) {
    u64 r; asm("fma.rn.f32x2 %0, %1, %2, %3;" : "=l"(r) : "l"(a), "l"(b), "l"(c)); return r;
}
__device__ __forceinline__ u64 shfl64(u64 v, int m) {
    float x, y; upk2(v, x, y);
    x = __shfl_xor_sync(0xffffffffu, x, m);
    y = __shfl_xor_sync(0xffffffffu, y, m);
    return pk2(x, y);
}

// packed-broadcast gate: m*v = fma(mi, swap(v), mul(mr, v))
struct PG { u64 r00, i00, r01, i01, r10, i10, r11, i11; };
__device__ __forceinline__ PG ldPG(const float4* p) {
    float4 a = p[0], b = p[1], c = p[2], d = p[3];
    PG g;
    g.r00 = pk2(a.x, a.y); g.i00 = pk2(a.z, a.w);
    g.r01 = pk2(b.x, b.y); g.i01 = pk2(b.z, b.w);
    g.r10 = pk2(c.x, c.y); g.i10 = pk2(c.z, c.w);
    g.r11 = pk2(d.x, d.y); g.i11 = pk2(d.z, d.w);
    return g;
}

// ---------------- prep kernels ----------------
__device__ __forceinline__ void store_packed(float4* dst, const M2& M) {
    dst[0] = make_float4(M.m00.x, M.m00.x, -M.m00.y, M.m00.y);
    dst[1] = make_float4(M.m01.x, M.m01.x, -M.m01.y, M.m01.y);
    dst[2] = make_float4(M.m10.x, M.m10.x, -M.m10.y, M.m10.y);
    dst[3] = make_float4(M.m11.x, M.m11.x, -M.m11.y, M.m11.y);
}

__global__ void prep_var_kernel(const float* __restrict__ theta) {
    int idx = blockIdx.x * blockDim.x + threadIdx.x;        // l*NQ + q
    if (idx >= LAYERS * NQ) return;
    const float* th = theta + idx * 3;
    M2 M = mmul(rz_m(th[2]), mmul(ry_m(th[1]), rx_m(th[0])));
    store_packed(&g_vm[idx * 4], M);
}

__global__ void prep_enc_kernel(const float* __restrict__ features, int B) {
    int idx = blockIdx.x * blockDim.x + threadIdx.x;        // e*B*NQ + b*NQ + q
    if (idx >= NENC * B * NQ) return;
    int q = idx % NQ;
    int b = (idx / NQ) % B;
    int e = idx / (B * NQ);
    float f = features[b * NQ + q];
    M2 R = (e & 1) ? ry_m(f) : rx_m(f);
    if (e >= 2) {
        const float r = 0.7071067811865476f;
        M2 H; H.m00 = {r, 0.f}; H.m01 = {r, 0.f}; H.m10 = {r, 0.f}; H.m11 = {-r, 0.f};
        R = mmul(R, H);
    }
    // first column of R(·H): gate applied to |0>
    g_em[idx] = make_float4(R.m00.x, R.m00.y, R.m10.x, R.m10.y);
}

// ---------------- register-resident gate primitives ----------------
// Amplitude index: i = (tid << 4) | k. Bits 0-3 = k (registers),
// bits 4-8 = lane, bits 9-11 = warp id.

template<int P>
__device__ __forceinline__ void gate_local(u64 s[16], const PG g) {
    #pragma unroll
    for (int k = 0; k < 16; k++) {
        if (!(k & (1 << P))) {
            const int k1 = k | (1 << P);
            u64 v0 = s[k], v1 = s[k1];
            u64 v0s = pswap(v0), v1s = pswap(v1);
            s[k]  = pfma(g.i01, v1s, pfma(g.r01, v1, pfma(g.i00, v0s, pmul(g.r00, v0))));
            s[k1] = pfma(g.i11, v1s, pfma(g.r11, v1, pfma(g.i10, v0s, pmul(g.r10, v0))));
        }
    }
}

__device__ __forceinline__ void gate_lane(u64 s[16], const PG g, int mask, int lane) {
    const bool hi = lane & mask;
    const u64 ar = hi ? g.r10 : g.r00;
    const u64 ai = hi ? g.i10 : g.i00;
    const u64 br = hi ? g.r11 : g.r01;
    const u64 bi = hi ? g.i11 : g.i01;
    #pragma unroll
    for (int k = 0; k < 16; k++) {
        u64 o  = shfl64(s[k], mask);
        u64 a0 = hi ? o : s[k];
        u64 a1 = hi ? s[k] : o;
        s[k] = pfma(bi, pswap(a1), pfma(br, a1, pfma(ai, pswap(a0), pmul(ar, a0))));
    }
}

__device__ __forceinline__ void gate_warp(u64 s[16], const PG g, int wmask,
                                          ulonglong2* xch, int tid, int w) {
    #pragma unroll
    for (int j = 0; j < 8; j++)
        xch[j * NT + tid] = make_ulonglong2(s[2*j], s[2*j+1]);
    __syncthreads();
    const bool hi = w & wmask;
    const u64 ar = hi ? g.r10 : g.r00;
    const u64 ai = hi ? g.i10 : g.i00;
    const u64 br = hi ? g.r11 : g.r01;
    const u64 bi = hi ? g.i11 : g.i01;
    const int ptid = tid ^ (wmask << 5);
    #pragma unroll
    for (int j = 0; j < 8; j++) {
        ulonglong2 v = xch[j * NT + ptid];
        u64 a0 = hi ? v.x : s[2*j];
        u64 a1 = hi ? s[2*j] : v.x;
        s[2*j] = pfma(bi, pswap(a1), pfma(br, a1, pfma(ai, pswap(a0), pmul(ar, a0))));
        a0 = hi ? v.y : s[2*j+1];
        a1 = hi ? s[2*j+1] : v.y;
        s[2*j+1] = pfma(bi, pswap(a1), pfma(br, a1, pfma(ai, pswap(a0), pmul(ar, a0))));
    }
    __syncthreads();
}

// 12-gate commuting sweep (variational), one matrix per qubit q=0..11
__device__ __forceinline__ void vsweep(const float4* mats, u64 s[16],
                                       ulonglong2* xch, int tid, int lane, int w) {
    gate_warp(s, ldPG(mats + 0),  4, xch, tid, w);   // q=0,  bit 11
    gate_warp(s, ldPG(mats + 4),  2, xch, tid, w);   // q=1,  bit 10
    gate_warp(s, ldPG(mats + 8),  1, xch, tid, w);   // q=2,  bit 9
    gate_lane(s, ldPG(mats + 12), 16, lane);         // q=3,  bit 8
    gate_lane(s, ldPG(mats + 16),  8, lane);         // q=4,  bit 7
    gate_lane(s, ldPG(mats + 20),  4, lane);         // q=5,  bit 6
    gate_lane(s, ldPG(mats + 24),  2, lane);         // q=6,  bit 5
    gate_lane(s, ldPG(mats + 28),  1, lane);         // q=7,  bit 4
    gate_local<3>(s, ldPG(mats + 32));               // q=8,  bit 3
    gate_local<2>(s, ldPG(mats + 36));               // q=9,  bit 2
    gate_local<1>(s, ldPG(mats + 40));               // q=10, bit 1
    gate_local<0>(s, ldPG(mats + 44));               // q=11, bit 0
}

// ---------------- CNOT primitives (control = higher bit, target = ctrl-1) --
template<int PC, int PT>
__device__ __forceinline__ void cnot_local(u64 s[16]) {
    #pragma unroll
    for (int k = 0; k < 16; k++) {
        if ((k & (1 << PC)) && !(k & (1 << PT))) {
            const int k1 = k | (1 << PT);
            u64 t = s[k]; s[k] = s[k1]; s[k1] = t;
        }
    }
}

__device__ __forceinline__ void cnot_lane(u64 s[16], int cmask, int tmask, int lane) {
    const bool c = lane & cmask;
    #pragma unroll
    for (int k = 0; k < 16; k++) {
        u64 o = shfl64(s[k], tmask);
        if (c) s[k] = o;
    }
}

// ctrl = lane bit 0 (bit 4), tgt = local bit 3: predicated register swap
__device__ __forceinline__ void cnot_lane_local(u64 s[16], int lane) {
    if (lane & 1) {
        #pragma unroll
        for (int k = 0; k < 8; k++) { u64 t = s[k]; s[k] = s[k + 8]; s[k + 8] = t; }
    }
}

// ctrl = warp bit 0 (bit 9), tgt = lane bit 4 (bit 8): warp-uniform shfl swap
__device__ __forceinline__ void cnot_w_lane(u64 s[16], int w) {
    if (w & 1) {
        #pragma unroll
        for (int k = 0; k < 16; k++) s[k] = shfl64(s[k], 16);
    }
}

// ctrl, tgt both warp bits: smem exchange between warp pairs with ctrl=1
__device__ __forceinline__ void cnot_warp(u64 s[16], int cmask, int tmask,
                                          ulonglong2* xch, int tid, int w) {
    const bool act = w & cmask;
    if (act) {
        #pragma unroll
        for (int j = 0; j < 8; j++)
            xch[j * NT + tid] = make_ulonglong2(s[2*j], s[2*j+1]);
    }
    __syncthreads();
    if (act) {
        const int ptid = tid ^ (tmask << 5);
        #pragma unroll
        for (int j = 0; j < 8; j++) {
            ulonglong2 v = xch[j * NT + ptid];
            s[2*j] = v.x; s[2*j+1] = v.y;
        }
    }
    __syncthreads();
}

// ---------------- main kernel ----------------
__global__ __launch_bounds__(NT, 2)
void vqc_reg_kernel(int B)
{
    __shared__ ulonglong2 xch[8 * NT];      // 32 KB exchange buffer
    __shared__ float      red[NWARP * NQ];

    const int b    = blockIdx.x;
    const int e    = blockIdx.y;
    const int tid  = threadIdx.x;
    const int lane = tid & 31;
    const int w    = tid >> 5;

    // ---- encoding: direct product-state construction (no sweep) ----
    // state[i] = prod_q col_q[bit_{11-q}(i)]; tid bits 7..0 = i bits 11..4.
    const float4* col = g_em + (e * B + b) * NQ;
    float2 ph;
    {
        float4 c0 = col[0];
        ph = ((tid >> 7) & 1) ? make_float2(c0.z, c0.w) : make_float2(c0.x, c0.y);
        #pragma unroll
        for (int q = 1; q < 8; q++) {
            float4 cq = col[q];
            float2 v = ((tid >> (7 - q)) & 1) ? make_float2(cq.z, cq.w)
                                              : make_float2(cq.x, cq.y);
            ph = cmul(ph, v);
        }
    }
    u64 s[16];
    {
        float4 c8 = col[8], c9 = col[9], c10 = col[10], c11 = col[11];
        float2 t2[2], t4[4], t8[8];
        t2[0] = cmul(ph, make_float2(c8.x, c8.y));
        t2[1] = cmul(ph, make_float2(c8.z, c8.w));
        #pragma unroll
        for (int i = 0; i < 2; i++) {
            t4[i*2+0] = cmul(t2[i], make_float2(c9.x, c9.y));
            t4[i*2+1] = cmul(t2[i], make_float2(c9.z, c9.w));
        }
        #pragma unroll
        for (int i = 0; i < 4; i++) {
            t8[i*2+0] = cmul(t4[i], make_float2(c10.x, c10.y));
            t8[i*2+1] = cmul(t4[i], make_float2(c10.z, c10.w));
        }
        #pragma unroll
        for (int i = 0; i < 8; i++) {
            float2 a = cmul(t8[i], make_float2(c11.x, c11.y));
            float2 bm = cmul(t8[i], make_float2(c11.z, c11.w));
            s[i*2+0] = pk2(a.x, a.y);
            s[i*2+1] = pk2(bm.x, bm.y);
        }
    }

    // ---- variational layers (packed f32x2 math) ----
    #pragma unroll 1
    for (int l = 0; l < LAYERS; l++) {
        vsweep(g_vm + (l * NQ) * 4, s, xch, tid, lane, w);
        // even ladder: q = 0,2,4,6,8,10 -> (11,10)(9,8)(7,6)(5,4)(3,2)(1,0)
        cnot_warp(s, 4, 2, xch, tid, w);     // (11,10)
        cnot_w_lane(s, w);                   // (9,8)
        cnot_lane(s, 8, 4, lane);            // (7,6)
        cnot_lane(s, 2, 1, lane);            // (5,4)
        cnot_local<3, 2>(s);                 // (3,2)
        cnot_local<1, 0>(s);                 // (1,0)
        // odd ladder: q = 1,3,5,7,9 -> (10,9)(8,7)(6,5)(4,3)(2,1)
        cnot_warp(s, 2, 1, xch, tid, w);     // (10,9)
        cnot_lane(s, 16, 8, lane);           // (8,7)
        cnot_lane(s, 4, 2, lane);            // (6,5)
        cnot_lane_local(s, lane);            // (4,3)
        cnot_local<2, 1>(s);                 // (2,1)
    }

    // ---- <Z_q> for all 12 qubits ----
    float t[16], tot = 0.f;
    #pragma unroll
    for (int k = 0; k < 16; k++) {
        float x, y; upk2(s[k], x, y);
        t[k] = fmaf(x, x, y * y);
        tot += t[k];
    }
    float ez[NQ];
    #pragma unroll
    for (int q = 0; q < 8; q++)          // bits 11..4: sign fixed per thread
        ez[q] = ((tid >> (7 - q)) & 1) ? -tot : tot;
    #pragma unroll
    for (int q = 8; q < 12; q++) {       // bits 3..0: sign varies over k
        const int P = 11 - q;
        float a = 0.f;
        #pragma unroll
        for (int k = 0; k < 16; k++) a += ((k >> P) & 1) ? -t[k] : t[k];
        ez[q] = a;
    }

    #pragma unroll
    for (int q = 0; q < NQ; q++)
        #pragma unroll
        for (int o = 16; o > 0; o >>= 1)
            ez[q] += __shfl_xor_sync(0xffffffffu, ez[q], o);

    if (lane == 0) {
        #pragma unroll
        for (int q = 0; q < NQ; q++) red[w * NQ + q] = ez[q];
    }
    __syncthreads();
    if (tid < NQ) {
        float acc = 0.f;
        #pragma unroll
        for (int j = 0; j < NWARP; j++) acc += red[j * NQ + tid];
        g_branch[(e * B + b) * NQ + tid] = acc;
    }
}

// ---------------- softmax(alpha)-weighted branch mix ----------------
__global__ void reduce_kernel(const float* __restrict__ alpha,
                              float* __restrict__ out, int B)
{
    int idx = blockIdx.x * blockDim.x + threadIdx.x;
    if (idx >= B * NQ) return;
    float a0 = alpha[0], a1 = alpha[1], a2 = alpha[2], a3 = alpha[3];
    float m  = fmaxf(fmaxf(a0, a1), fmaxf(a2, a3));
    float w0 = expf(a0 - m), w1 = expf(a1 - m), w2 = expf(a2 - m), w3 = expf(a3 - m);
    float inv = 1.f / (w0 + w1 + w2 + w3);
    int stride = B * NQ;
    float y = w0 * g_branch[idx]
            + w1 * g_branch[stride + idx]
            + w2 * g_branch[2 * stride + idx]
            + w3 * g_branch[3 * stride + idx];
    out[idx] = y * inv;
}

extern "C" void kernel_launch(void* const* d_in, const int* in_sizes, int n_in,
                              void* d_out, int out_size)
{
    const float* features = (const float*)d_in[0];   // (B, 12)
    const float* theta    = (const float*)d_in[1];   // (4, 12, 3)
    const float* alpha    = (const float*)d_in[2];   // (4,)
    float* out = (float*)d_out;                      // (B, 12)

    int B = in_sizes[0] / NQ;
    if (B > MAXB) B = MAXB;

    prep_var_kernel<<<1, 64>>>(theta);
    int nenc = NENC * B * NQ;
    prep_enc_kernel<<<(nenc + 255) / 256, 256>>>(features, B);

    dim3 grid(B, NENC);
    vqc_reg_kernel<<<grid, NT>>>(B);

    int n = B * NQ;
    reduce_kernel<<<(n + 255) / 256, 256>>>(alpha, out, B);
}

// round 8
// speedup vs baseline: 2.5487x; 1.2341x over previous
#include <cuda_runtime.h>

#define NQ      12
#define NT      256
#define NWARP   8
#define LAYERS  4
#define NENC    4
#define MAXB    1024

typedef unsigned long long u64;

// ---------------- static device scratch (no allocations) ----------------
__device__ float  g_branch[NENC * MAXB * NQ];
// variational gates, packed-broadcast form: 4 float4 per gate
//   f4[m] = (re, re, -im, im) for m in {m00, m01, m10, m11}
__device__ float4 g_vm[LAYERS * NQ * 4];
// encoding: first column of R(·H) per (e,b,q): (c0.x, c0.y, c1.x, c1.y)
__device__ float4 g_em[NENC * MAXB * NQ];

// ---------------- scalar complex helpers (prep + encoding) ----------------
__device__ __forceinline__ float2 cmul(float2 a, float2 b) {
    return make_float2(fmaf(a.x, b.x, -a.y * b.y), fmaf(a.x, b.y, a.y * b.x));
}
__device__ __forceinline__ float2 cadd(float2 a, float2 b) {
    return make_float2(a.x + b.x, a.y + b.y);
}
struct M2 { float2 m00, m01, m10, m11; };
__device__ __forceinline__ M2 mmul(const M2& A, const M2& B) {
    M2 C;
    C.m00 = cadd(cmul(A.m00, B.m00), cmul(A.m01, B.m10));
    C.m01 = cadd(cmul(A.m00, B.m01), cmul(A.m01, B.m11));
    C.m10 = cadd(cmul(A.m10, B.m00), cmul(A.m11, B.m10));
    C.m11 = cadd(cmul(A.m10, B.m01), cmul(A.m11, B.m11));
    return C;
}
__device__ __forceinline__ M2 rx_m(float t) {
    float s, c; sincosf(0.5f * t, &s, &c);
    M2 M; M.m00 = {c, 0.f}; M.m01 = {0.f, -s}; M.m10 = {0.f, -s}; M.m11 = {c, 0.f};
    return M;
}
__device__ __forceinline__ M2 ry_m(float t) {
    float s, c; sincosf(0.5f * t, &s, &c);
    M2 M; M.m00 = {c, 0.f}; M.m01 = {-s, 0.f}; M.m10 = {s, 0.f}; M.m11 = {c, 0.f};
    return M;
}
__device__ __forceinline__ M2 rz_m(float t) {
    float s, c; sincosf(0.5f * t, &s, &c);
    M2 M; M.m00 = {c, -s}; M.m01 = {0.f, 0.f}; M.m10 = {0.f, 0.f}; M.m11 = {c, s};
    return M;
}

// ---------------- packed f32x2 primitives ----------------
__device__ __forceinline__ u64 pk2(float x, float y) {
    u64 r; asm("mov.b64 %0, {%1, %2};" : "=l"(r) : "f"(x), "f"(y)); return r;
}
__device__ __forceinline__ void upk2(u64 v, float& x, float& y) {
    asm("mov.b64 {%0, %1}, %2;" : "=f"(x), "=f"(y) : "l"(v));
}
__device__ __forceinline__ u64 pswap(u64 v) {           // (x,y) -> (y,x)
    float x, y; upk2(v, x, y); return pk2(y, x);
}
__device__ __forceinline__ u64 pmul(u64 a, u64 b) {
    u64 r; asm("mul.rn.f32x2 %0, %1, %2;" : "=l"(r) : "l"(a), "l"(b)); return r;
}
__device__ __forceinline__ u64 pfma(u64 a, u64 b, u64 c) {
    u64 r; asm("fma.rn.f32x2 %0, %1, %2, %3;" : "=l"(r) : "l"(a), "l"(b), "l"(c)); return r;
}
__device__ __forceinline__ u64 shfl64(u64 v, int m) {
    float x, y; upk2(v, x, y);
    x = __shfl_xor_sync(0xffffffffu, x, m);
    y = __shfl_xor_sync(0xffffffffu, y, m);
    return pk2(x, y);
}

// packed-broadcast gate: m*v = fma(mi, swap(v), mul(mr, v))
struct PG { u64 r00, i00, r01, i01, r10, i10, r11, i11; };
__device__ __forceinline__ PG ldPG(const float4* p) {
    float4 a = p[0], b = p[1], c = p[2], d = p[3];
    PG g;
    g.r00 = pk2(a.x, a.y); g.i00 = pk2(a.z, a.w);
    g.r01 = pk2(b.x, b.y); g.i01 = pk2(b.z, b.w);
    g.r10 = pk2(c.x, c.y); g.i10 = pk2(c.z, c.w);
    g.r11 = pk2(d.x, d.y); g.i11 = pk2(d.z, d.w);
    return g;
}
// swap matrix columns when p (absorbs a preceding CNOT on this wire)
__device__ __forceinline__ PG pg_colswap(const PG& g, bool p) {
    PG h;
    h.r00 = p ? g.r01 : g.r00; h.i00 = p ? g.i01 : g.i00;
    h.r01 = p ? g.r00 : g.r01; h.i01 = p ? g.i00 : g.i01;
    h.r10 = p ? g.r11 : g.r10; h.i10 = p ? g.i11 : g.i10;
    h.r11 = p ? g.r10 : g.r11; h.i11 = p ? g.i10 : g.i11;
    return h;
}

// ---------------- prep kernels ----------------
__device__ __forceinline__ void store_packed(float4* dst, const M2& M) {
    dst[0] = make_float4(M.m00.x, M.m00.x, -M.m00.y, M.m00.y);
    dst[1] = make_float4(M.m01.x, M.m01.x, -M.m01.y, M.m01.y);
    dst[2] = make_float4(M.m10.x, M.m10.x, -M.m10.y, M.m10.y);
    dst[3] = make_float4(M.m11.x, M.m11.x, -M.m11.y, M.m11.y);
}

__global__ void prep_var_kernel(const float* __restrict__ theta) {
    int idx = blockIdx.x * blockDim.x + threadIdx.x;        // l*NQ + q
    if (idx >= LAYERS * NQ) return;
    const float* th = theta + idx * 3;
    M2 M = mmul(rz_m(th[2]), mmul(ry_m(th[1]), rx_m(th[0])));
    store_packed(&g_vm[idx * 4], M);
}

__global__ void prep_enc_kernel(const float* __restrict__ features, int B) {
    int idx = blockIdx.x * blockDim.x + threadIdx.x;        // e*B*NQ + b*NQ + q
    if (idx >= NENC * B * NQ) return;
    int q = idx % NQ;
    int b = (idx / NQ) % B;
    int e = idx / (B * NQ);
    float f = features[b * NQ + q];
    M2 R = (e & 1) ? ry_m(f) : rx_m(f);
    if (e >= 2) {
        const float r = 0.7071067811865476f;
        M2 H; H.m00 = {r, 0.f}; H.m01 = {r, 0.f}; H.m10 = {r, 0.f}; H.m11 = {-r, 0.f};
        R = mmul(R, H);
    }
    g_em[idx] = make_float4(R.m00.x, R.m00.y, R.m10.x, R.m10.y);
}

// ---------------- fused register-resident gate primitives ----------------
// Amplitude index: i = (tid << 4) | k. Bits 0-3 = k (registers),
// bits 4-8 = lane, bits 9-11 = warp id.
// Fusion semantics:
//   CPRE  (column swap, pred): CNOT(ctrl, this wire) applied BEFORE this gate
//   CPOST (row swap, pred):    CNOT(ctrl, this wire) applied AFTER this gate

template<int P, int CPRE, int CPOST>
__device__ __forceinline__ void gate_localf(u64 s[16], const PG g) {
    #pragma unroll
    for (int k = 0; k < 16; k++) {
        if (!(k & (1 << P))) {
            const int k1 = k | (1 << P);
            const bool pre  = (CPRE  >= 0) && ((k >> (CPRE  < 0 ? 0 : CPRE))  & 1);
            const bool post = (CPOST >= 0) && ((k >> (CPOST < 0 ? 0 : CPOST)) & 1);
            u64 v0 = pre ? s[k1] : s[k];
            u64 v1 = pre ? s[k]  : s[k1];
            u64 v0s = pswap(v0), v1s = pswap(v1);
            u64 o0 = pfma(g.i01, v1s, pfma(g.r01, v1, pfma(g.i00, v0s, pmul(g.r00, v0))));
            u64 o1 = pfma(g.i11, v1s, pfma(g.r11, v1, pfma(g.i10, v0s, pmul(g.r10, v0))));
            s[post ? k1 : k] = o0;
            s[post ? k  : k1] = o1;
        }
    }
}

__device__ __forceinline__ void gate_lanef(u64 s[16], PG g, int mask, int lane,
                                           bool cswap, bool rxor) {
    g = pg_colswap(g, cswap);
    const bool hi  = (lane & mask) != 0;
    const bool row = hi ^ rxor;
    const u64 ar = row ? g.r10 : g.r00;
    const u64 ai = row ? g.i10 : g.i00;
    const u64 br = row ? g.r11 : g.r01;
    const u64 bi = row ? g.i11 : g.i01;
    #pragma unroll
    for (int k = 0; k < 16; k++) {
        u64 o  = shfl64(s[k], mask);
        u64 a0 = hi ? o : s[k];
        u64 a1 = hi ? s[k] : o;
        s[k] = pfma(bi, pswap(a1), pfma(br, a1, pfma(ai, pswap(a0), pmul(ar, a0))));
    }
}

__device__ __forceinline__ void gate_warpf(u64 s[16], PG g, int wmask,
                                           ulonglong2* xch, int tid, int w,
                                           bool cswap, bool rxor) {
    #pragma unroll
    for (int j = 0; j < 8; j++)
        xch[j * NT + tid] = make_ulonglong2(s[2*j], s[2*j+1]);
    __syncthreads();
    g = pg_colswap(g, cswap);
    const bool hi  = (w & wmask) != 0;
    const bool row = hi ^ rxor;
    const u64 ar = row ? g.r10 : g.r00;
    const u64 ai = row ? g.i10 : g.i00;
    const u64 br = row ? g.r11 : g.r01;
    const u64 bi = row ? g.i11 : g.i01;
    const int ptid = tid ^ (wmask << 5);
    #pragma unroll
    for (int j = 0; j < 8; j++) {
        ulonglong2 v = xch[j * NT + ptid];
        u64 a0 = hi ? v.x : s[2*j];
        u64 a1 = hi ? s[2*j] : v.x;
        s[2*j] = pfma(bi, pswap(a1), pfma(br, a1, pfma(ai, pswap(a0), pmul(ar, a0))));
        a0 = hi ? v.y : s[2*j+1];
        a1 = hi ? s[2*j+1] : v.y;
        s[2*j+1] = pfma(bi, pswap(a1), pfma(br, a1, pfma(ai, pswap(a0), pmul(ar, a0))));
    }
    __syncthreads();
}

// Fused sweep. First half: even wires (bits 11,9,7,5,3,1), absorbing the
// PREVIOUS layer's odd-ladder CNOTs (col swaps, enabled by PRE). Second half:
// odd wires (bits 10,8,6,4,2,0), absorbing THIS layer's even-ladder CNOTs
// (row swaps). Odd-ladder of this layer is deferred to the next sweep/epilogue.
template<bool PRE>
__device__ __forceinline__ void vsweepf(const float4* mats, u64 s[16],
                                        ulonglong2* xch, int tid, int lane, int w) {
    // ---- first half: even wires ----
    gate_warpf(s, ldPG(mats + 0*4),  4, xch, tid, w, false, false);            // w0  b11
    gate_warpf(s, ldPG(mats + 2*4),  1, xch, tid, w, PRE && (w & 2), false);   // w2  b9,  pre c=b10
    gate_lanef(s, ldPG(mats + 4*4),  8, lane, PRE && (lane & 16), false);      // w4  b7,  pre c=b8
    gate_lanef(s, ldPG(mats + 6*4),  2, lane, PRE && (lane & 4),  false);      // w6  b5,  pre c=b6
    {                                                                          // w8  b3,  pre c=b4
        PG g = ldPG(mats + 8*4);
        g = pg_colswap(g, PRE && (lane & 1));
        gate_localf<3, -1, -1>(s, g);
    }
    if (PRE) gate_localf<1, 2, -1>(s, ldPG(mats + 10*4));                      // w10 b1,  pre c=b2
    else     gate_localf<1, -1, -1>(s, ldPG(mats + 10*4));
    // ---- second half: odd wires, even-ladder CNOT fused as row swap ----
    gate_warpf(s, ldPG(mats + 1*4),  2, xch, tid, w, false, (w & 4) != 0);     // w1  b10, post c=b11
    gate_lanef(s, ldPG(mats + 3*4), 16, lane, false, (w & 1) != 0);            // w3  b8,  post c=b9
    gate_lanef(s, ldPG(mats + 5*4),  4, lane, false, (lane & 8) != 0);         // w5  b6,  post c=b7
    gate_lanef(s, ldPG(mats + 7*4),  1, lane, false, (lane & 2) != 0);         // w7  b4,  post c=b5
    gate_localf<2, -1, 3>(s, ldPG(mats + 9*4));                                // w9  b2,  post c=b3
    gate_localf<0, -1, 1>(s, ldPG(mats + 11*4));                               // w11 b0,  post c=b1
}

// ---------------- main kernel ----------------
__global__ __launch_bounds__(NT, 2)
void vqc_reg_kernel(int B)
{
    __shared__ ulonglong2 xch[8 * NT];      // 32 KB exchange buffer
    __shared__ float      red[NWARP * NQ];

    const int b    = blockIdx.x;
    const int e    = blockIdx.y;
    const int tid  = threadIdx.x;
    const int lane = tid & 31;
    const int w    = tid >> 5;

    // ---- encoding: direct product-state construction (no sweep) ----
    const float4* col = g_em + (e * B + b) * NQ;
    float2 ph;
    {
        float4 c0 = col[0];
        ph = ((tid >> 7) & 1) ? make_float2(c0.z, c0.w) : make_float2(c0.x, c0.y);
        #pragma unroll
        for (int q = 1; q < 8; q++) {
            float4 cq = col[q];
            float2 v = ((tid >> (7 - q)) & 1) ? make_float2(cq.z, cq.w)
                                              : make_float2(cq.x, cq.y);
            ph = cmul(ph, v);
        }
    }
    u64 s[16];
    {
        float4 c8 = col[8], c9 = col[9], c10 = col[10], c11 = col[11];
        float2 t2[2], t4[4], t8[8];
        t2[0] = cmul(ph, make_float2(c8.x, c8.y));
        t2[1] = cmul(ph, make_float2(c8.z, c8.w));
        #pragma unroll
        for (int i = 0; i < 2; i++) {
            t4[i*2+0] = cmul(t2[i], make_float2(c9.x, c9.y));
            t4[i*2+1] = cmul(t2[i], make_float2(c9.z, c9.w));
        }
        #pragma unroll
        for (int i = 0; i < 4; i++) {
            t8[i*2+0] = cmul(t4[i], make_float2(c10.x, c10.y));
            t8[i*2+1] = cmul(t4[i], make_float2(c10.z, c10.w));
        }
        #pragma unroll
        for (int i = 0; i < 8; i++) {
            float2 a  = cmul(t8[i], make_float2(c11.x, c11.y));
            float2 bm = cmul(t8[i], make_float2(c11.z, c11.w));
            s[i*2+0] = pk2(a.x, a.y);
            s[i*2+1] = pk2(bm.x, bm.y);
        }
    }

    // ---- variational layers, CNOTs fully fused into sweeps ----
    vsweepf<false>(g_vm + 0 * NQ * 4, s, xch, tid, lane, w);
    vsweepf<true >(g_vm + 1 * NQ * 4, s, xch, tid, lane, w);
    vsweepf<true >(g_vm + 2 * NQ * 4, s, xch, tid, lane, w);
    vsweepf<true >(g_vm + 3 * NQ * 4, s, xch, tid, lane, w);
    // remaining: layer-3 odd-ladder CNOTs -> folded into epilogue signs:
    //   b9^=b10, b7^=b8, b5^=b6, b3^=b4, b1^=b2

    // ---- <Z_q> for all 12 qubits (signs use permuted bits) ----
    float t[16], tot = 0.f;
    #pragma unroll
    for (int k = 0; k < 16; k++) {
        float x, y; upk2(s[k], x, y);
        t[k] = fmaf(x, x, y * y);
        tot += t[k];
    }
    const int t7 = (tid >> 7) & 1, t6 = (tid >> 6) & 1, t5 = (tid >> 5) & 1,
              t4b = (tid >> 4) & 1, t3 = (tid >> 3) & 1, t2b = (tid >> 2) & 1,
              t1 = (tid >> 1) & 1, t0 = tid & 1;
    float ez[NQ];
    ez[0] = t7        ? -tot : tot;   // bit 11
    ez[1] = t6        ? -tot : tot;   // bit 10
    ez[2] = (t5 ^ t6) ? -tot : tot;   // bit 9 ^ bit 10
    ez[3] = t4b       ? -tot : tot;   // bit 8
    ez[4] = (t3 ^ t4b)? -tot : tot;   // bit 7 ^ bit 8
    ez[5] = t2b       ? -tot : tot;   // bit 6
    ez[6] = (t1 ^ t2b)? -tot : tot;   // bit 5 ^ bit 6
    ez[7] = t0        ? -tot : tot;   // bit 4
    float a8 = 0.f, a9 = 0.f, a10 = 0.f, a11 = 0.f;
    #pragma unroll
    for (int k = 0; k < 16; k++) {
        a8  += (k & 8) ? -t[k] : t[k];                      // k bit 3
        a9  += (k & 4) ? -t[k] : t[k];                      // k bit 2
        a10 += (((k >> 1) ^ (k >> 2)) & 1) ? -t[k] : t[k];  // k bit1 ^ bit2
        a11 += (k & 1) ? -t[k] : t[k];                      // k bit 0
    }
    ez[8]  = t0 ? -a8 : a8;           // (bit 3 ^ bit 4); bit4 = tid bit 0
    ez[9]  = a9;
    ez[10] = a10;
    ez[11] = a11;

    #pragma unroll
    for (int q = 0; q < NQ; q++)
        #pragma unroll
        for (int o = 16; o > 0; o >>= 1)
            ez[q] += __shfl_xor_sync(0xffffffffu, ez[q], o);

    if (lane == 0) {
        #pragma unroll
        for (int q = 0; q < NQ; q++) red[w * NQ + q] = ez[q];
    }
    __syncthreads();
    if (tid < NQ) {
        float acc = 0.f;
        #pragma unroll
        for (int j = 0; j < NWARP; j++) acc += red[j * NQ + tid];
        g_branch[(e * B + b) * NQ + tid] = acc;
    }
}

// ---------------- softmax(alpha)-weighted branch mix ----------------
__global__ void reduce_kernel(const float* __restrict__ alpha,
                              float* __restrict__ out, int B)
{
    int idx = blockIdx.x * blockDim.x + threadIdx.x;
    if (idx >= B * NQ) return;
    float a0 = alpha[0], a1 = alpha[1], a2 = alpha[2], a3 = alpha[3];
    float m  = fmaxf(fmaxf(a0, a1), fmaxf(a2, a3));
    float w0 = expf(a0 - m), w1 = expf(a1 - m), w2 = expf(a2 - m), w3 = expf(a3 - m);
    float inv = 1.f / (w0 + w1 + w2 + w3);
    int stride = B * NQ;
    float y = w0 * g_branch[idx]
            + w1 * g_branch[stride + idx]
            + w2 * g_branch[2 * stride + idx]
            + w3 * g_branch[3 * stride + idx];
    out[idx] = y * inv;
}

extern "C" void kernel_launch(void* const* d_in, const int* in_sizes, int n_in,
                              void* d_out, int out_size)
{
    const float* features = (const float*)d_in[0];   // (B, 12)
    const float* theta    = (const float*)d_in[1];   // (4, 12, 3)
    const float* alpha    = (const float*)d_in[2];   // (4,)
    float* out = (float*)d_out;                      // (B, 12)

    int B = in_sizes[0] / NQ;
    if (B > MAXB) B = MAXB;

    prep_var_kernel<<<1, 64>>>(theta);
    int nenc = NENC * B * NQ;
    prep_enc_kernel<<<(nenc + 255) / 256, 256>>>(features, B);

    dim3 grid(B, NENC);
    vqc_reg_kernel<<<grid, NT>>>(B);

    int n = B * NQ;
    reduce_kernel<<<(n + 255) / 256, 256>>>(alpha, out, B);
}

// round 9
// speedup vs baseline: 2.8086x; 1.1020x over previous
#include <cuda_runtime.h>

#define NQ      12
#define NT      256
#define NWARP   8
#define LAYERS  4
#define NENC    4
#define MAXB    1024

typedef unsigned long long u64;

// ---------------- static device scratch (no allocations) ----------------
__device__ float g_branch[NENC * MAXB * NQ];
// variational gates: 12 u64 broadcast coefficients per gate (see prep)
__device__ u64   g_vm[LAYERS * 12 * 12];
// encoding: first column of R(·H) per (e,b,q): (c0.x, c0.y, c1.x, c1.y)
__device__ float4 g_em[NENC * MAXB * NQ];

// ---------------- scalar complex helpers (prep + encoding) ----------------
__device__ __forceinline__ float2 cmul(float2 a, float2 b) {
    return make_float2(fmaf(a.x, b.x, -a.y * b.y), fmaf(a.x, b.y, a.y * b.x));
}
__device__ __forceinline__ float2 cadd(float2 a, float2 b) {
    return make_float2(a.x + b.x, a.y + b.y);
}
struct M2 { float2 m00, m01, m10, m11; };
__device__ __forceinline__ M2 mmul(const M2& A, const M2& B) {
    M2 C;
    C.m00 = cadd(cmul(A.m00, B.m00), cmul(A.m01, B.m10));
    C.m01 = cadd(cmul(A.m00, B.m01), cmul(A.m01, B.m11));
    C.m10 = cadd(cmul(A.m10, B.m00), cmul(A.m11, B.m10));
    C.m11 = cadd(cmul(A.m10, B.m01), cmul(A.m11, B.m11));
    return C;
}
__device__ __forceinline__ M2 rx_m(float t) {
    float s, c; sincosf(0.5f * t, &s, &c);
    M2 M; M.m00 = {c, 0.f}; M.m01 = {0.f, -s}; M.m10 = {0.f, -s}; M.m11 = {c, 0.f};
    return M;
}
__device__ __forceinline__ M2 ry_m(float t) {
    float s, c; sincosf(0.5f * t, &s, &c);
    M2 M; M.m00 = {c, 0.f}; M.m01 = {-s, 0.f}; M.m10 = {s, 0.f}; M.m11 = {c, 0.f};
    return M;
}
__device__ __forceinline__ M2 rz_m(float t) {
    float s, c; sincosf(0.5f * t, &s, &c);
    M2 M; M.m00 = {c, -s}; M.m01 = {0.f, 0.f}; M.m10 = {0.f, 0.f}; M.m11 = {c, s};
    return M;
}

// ---------------- packed f32x2 primitives ----------------
__device__ __forceinline__ u64 pk2(float x, float y) {
    u64 r; asm("mov.b64 %0, {%1, %2};" : "=l"(r) : "f"(x), "f"(y)); return r;
}
__device__ __forceinline__ void upk2(u64 v, float& x, float& y) {
    asm("mov.b64 {%0, %1}, %2;" : "=f"(x), "=f"(y) : "l"(v));
}
__device__ __forceinline__ u64 pswap(u64 v) {           // (x,y) -> (y,x)
    float x, y; upk2(v, x, y); return pk2(y, x);
}
__device__ __forceinline__ u64 pmul(u64 a, u64 b) {
    u64 r; asm("mul.rn.f32x2 %0, %1, %2;" : "=l"(r) : "l"(a), "l"(b)); return r;
}
__device__ __forceinline__ u64 pfma(u64 a, u64 b, u64 c) {
    u64 r; asm("fma.rn.f32x2 %0, %1, %2, %3;" : "=l"(r) : "l"(a), "l"(b), "l"(c)); return r;
}
__device__ __forceinline__ u64 shfl64(u64 v, int m) {
    float x, y; upk2(v, x, y);
    x = __shfl_xor_sync(0xffffffffu, x, m);
    y = __shfl_xor_sync(0xffffffffu, y, m);
    return pk2(x, y);
}

// broadcast coefficient triple for one matrix element: (r,r), (i,i), (-i,-i)
struct Tri { u64 r, i, ni; };

// gate layout in g_vm (wires 0..10): e[m] = element m00,m01,m10,m11 at
// offsets m*3: [r2, i2, ni2]. Wire 11 has a special layout (see prep).
__device__ __forceinline__ void ldGate(const u64* __restrict__ p, Tri e[4]) {
    const ulonglong2* v = (const ulonglong2*)p;
    ulonglong2 v0 = v[0], v1 = v[1], v2 = v[2], v3 = v[3], v4 = v[4], v5 = v[5];
    e[0].r = v0.x; e[0].i = v0.y; e[0].ni = v1.x;
    e[1].r = v1.y; e[1].i = v2.x; e[1].ni = v2.y;
    e[2].r = v3.x; e[2].i = v3.y; e[2].ni = v4.x;
    e[3].r = v4.y; e[3].i = v5.x; e[3].ni = v5.y;
}
__device__ __forceinline__ void tri_colswap(Tri e[4], bool p) {
    Tri t0 = p ? e[1] : e[0], t1 = p ? e[0] : e[1];
    Tri t2 = p ? e[3] : e[2], t3 = p ? e[2] : e[3];
    e[0] = t0; e[1] = t1; e[2] = t2; e[3] = t3;
}

// ---------------- prep kernels ----------------
__global__ void prep_var_kernel(const float* __restrict__ theta) {
    int idx = blockIdx.x * blockDim.x + threadIdx.x;        // l*NQ + q
    if (idx >= LAYERS * NQ) return;
    int q = idx % NQ;
    const float* th = theta + idx * 3;
    M2 M = mmul(rz_m(th[2]), mmul(ry_m(th[1]), rx_m(th[0])));
    u64* dst = g_vm + idx * 12;
    if (q < 11) {
        float2 el[4] = { M.m00, M.m01, M.m10, M.m11 };
        #pragma unroll
        for (int m = 0; m < 4; m++) {
            dst[m*3+0] = pk2(el[m].x, el[m].x);
            dst[m*3+1] = pk2(el[m].y, el[m].y);
            dst[m*3+2] = pk2(-el[m].y, -el[m].y);
        }
    } else {
        // wire-11 (amp bit 0, within-u64) gate: diag/offdiag packed sets.
        // Set A (even j, normal), set B (odd j, row-swapped: absorbs the
        // post CNOT(ctrl=bit1) output swap).
        float r00 = M.m00.x, i00 = M.m00.y, r01 = M.m01.x, i01 = M.m01.y;
        float r10 = M.m10.x, i10 = M.m10.y, r11 = M.m11.x, i11 = M.m11.y;
        dst[0]  = pk2(r00, r11);  dst[1]  = pk2(r01, r10);
        dst[2]  = pk2(-i00, -i11); dst[3] = pk2(-i01, -i10);
        dst[4]  = pk2(i00, i11);  dst[5]  = pk2(i01, i10);
        dst[6]  = pk2(r10, r01);  dst[7]  = pk2(r11, r00);
        dst[8]  = pk2(-i10, -i01); dst[9] = pk2(-i11, -i00);
        dst[10] = pk2(i10, i01);  dst[11] = pk2(i11, i00);
    }
}

__global__ void prep_enc_kernel(const float* __restrict__ features, int B) {
    int idx = blockIdx.x * blockDim.x + threadIdx.x;        // e*B*NQ + b*NQ + q
    if (idx >= NENC * B * NQ) return;
    int q = idx % NQ;
    int b = (idx / NQ) % B;
    int e = idx / (B * NQ);
    float f = features[b * NQ + q];
    M2 R = (e & 1) ? ry_m(f) : rx_m(f);
    if (e >= 2) {
        const float r = 0.7071067811865476f;
        M2 H; H.m00 = {r, 0.f}; H.m01 = {r, 0.f}; H.m10 = {r, 0.f}; H.m11 = {-r, 0.f};
        R = mmul(R, H);
    }
    g_em[idx] = make_float4(R.m00.x, R.m00.y, R.m10.x, R.m10.y);
}

// ---------------- SoA register-resident gate primitives ----------------
// Amplitude index: i = (tid << 4) | (j << 1) | h.
//   h (bit 0): packed inside each u64 lane-pair
//   j bits 0..2 -> amp bits 1..3 (register index)
//   lane bits 0..4 -> amp bits 4..8; warp bits 0..2 -> amp bits 9..11
// State: sr[8], si[8] (u64 each): sr[j] = (re(i,h=0), re(i,h=1)), si = imag.

// gate on a j bit. PREJ/POSTJ: j-bit masks for fused CNOT col/row swaps.
template<int JB, int PREJ, int POSTJ>
__device__ __forceinline__ void gate_j(u64 sr[8], u64 si[8], const Tri e[4]) {
    #pragma unroll
    for (int j = 0; j < 8; j++) {
        if (!(j & JB)) {
            const int j1 = j | JB;
            const bool pre  = (PREJ != 0) && ((j & PREJ) != 0);
            const bool post = (POSTJ != 0) && ((j & POSTJ) != 0);
            const int ja = pre ? j1 : j, jb = pre ? j : j1;
            u64 Ar = sr[ja], Ai = si[ja], Br = sr[jb], Bi = si[jb];
            u64 o0r = pfma(e[1].ni, Bi, pfma(e[1].r, Br, pfma(e[0].ni, Ai, pmul(e[0].r, Ar))));
            u64 o0i = pfma(e[1].r,  Bi, pfma(e[1].i, Br, pfma(e[0].r,  Ai, pmul(e[0].i, Ar))));
            u64 o1r = pfma(e[3].ni, Bi, pfma(e[3].r, Br, pfma(e[2].ni, Ai, pmul(e[2].r, Ar))));
            u64 o1i = pfma(e[3].r,  Bi, pfma(e[3].i, Br, pfma(e[2].r,  Ai, pmul(e[2].i, Ar))));
            sr[post ? j1 : j]  = o0r; si[post ? j1 : j]  = o0i;
            sr[post ? j : j1]  = o1r; si[post ? j : j1]  = o1i;
        }
    }
}

// select self/other coefficient triples once per gate:
//   row = hi ^ rxor (post-CNOT row swap), cs = hi ^ cswap (pre-CNOT col swap)
//   self = M[row][cs], other = M[row][cs^1]
__device__ __forceinline__ void pick_pq(const Tri e[4], bool hi, bool cswap, bool rxor,
                                        Tri& P, Tri& Q) {
    const bool row = hi ^ rxor, cs = hi ^ cswap;
    Tri r0 = row ? e[2] : e[0];
    Tri r1 = row ? e[3] : e[1];
    P = cs ? r1 : r0;
    Q = cs ? r0 : r1;
}

__device__ __forceinline__ void gate_lane(u64 sr[8], u64 si[8], const Tri e[4],
                                          int mask, int lane, bool cswap, bool rxor) {
    const bool hi = (lane & mask) != 0;
    Tri P, Q; pick_pq(e, hi, cswap, rxor, P, Q);
    #pragma unroll
    for (int j = 0; j < 8; j++) {
        u64 orr = shfl64(sr[j], mask);
        u64 oii = shfl64(si[j], mask);
        u64 nr = pfma(Q.ni, oii, pfma(Q.r, orr, pfma(P.ni, si[j], pmul(P.r, sr[j]))));
        u64 nm = pfma(Q.r,  oii, pfma(Q.i, orr, pfma(P.r,  si[j], pmul(P.i, sr[j]))));
        sr[j] = nr; si[j] = nm;
    }
}

__device__ __forceinline__ void gate_warp(u64 sr[8], u64 si[8], const Tri e[4],
                                          int wmask, ulonglong2* xch, int tid, int w,
                                          bool cswap, bool rxor) {
    #pragma unroll
    for (int j = 0; j < 8; j++)
        xch[j * NT + tid] = make_ulonglong2(sr[j], si[j]);
    __syncthreads();
    const bool hi = (w & wmask) != 0;
    Tri P, Q; pick_pq(e, hi, cswap, rxor, P, Q);
    const int ptid = tid ^ (wmask << 5);
    #pragma unroll
    for (int j = 0; j < 8; j++) {
        ulonglong2 o = xch[j * NT + ptid];
        u64 nr = pfma(Q.ni, o.y, pfma(Q.r, o.x, pfma(P.ni, si[j], pmul(P.r, sr[j]))));
        u64 nm = pfma(Q.r,  o.y, pfma(Q.i, o.x, pfma(P.r,  si[j], pmul(P.i, sr[j]))));
        sr[j] = nr; si[j] = nm;
    }
    __syncthreads();
}

// wire-11 gate on amp bit 0 (within-u64), post CNOT(ctrl=bit1) fused via
// row-swapped set B for odd j. c = 12 u64 (set A at 0, set B at 6).
__device__ __forceinline__ void gate_h(u64 sr[8], u64 si[8], const u64* __restrict__ cp) {
    u64 c[12];
    const ulonglong2* v = (const ulonglong2*)cp;
    #pragma unroll
    for (int m = 0; m < 6; m++) { ulonglong2 t = v[m]; c[2*m] = t.x; c[2*m+1] = t.y; }
    #pragma unroll
    for (int j = 0; j < 8; j++) {
        const int o = (j & 1) ? 6 : 0;
        u64 rd = c[o+0], rs = c[o+1], nid = c[o+2], nis = c[o+3], id = c[o+4], is = c[o+5];
        u64 swr = pswap(sr[j]), swi = pswap(si[j]);
        u64 nr = pfma(nis, swi, pfma(nid, si[j], pfma(rs, swr, pmul(rd, sr[j]))));
        u64 nm = pfma(rs,  swi, pfma(rd,  si[j], pfma(is, swr, pmul(id, sr[j]))));
        sr[j] = nr; si[j] = nm;
    }
}

// Fused sweep (R7 scheme). First half: even wires, absorbing the PREVIOUS
// layer's odd-ladder CNOTs (col swaps when PRE). Second half: odd wires,
// absorbing THIS layer's even-ladder CNOTs (row swaps). This layer's odd
// ladder defers to the next sweep / epilogue.
template<bool PRE>
__device__ __forceinline__ void vsweepf(const u64* __restrict__ mats,
                                        u64 sr[8], u64 si[8],
                                        ulonglong2* xch, int tid, int lane, int w) {
    Tri e[4];
    // ---- first half: even wires ----
    ldGate(mats + 0*12, e);  gate_warp(sr, si, e, 4, xch, tid, w, false, false);          // w0  b11
    ldGate(mats + 2*12, e);  gate_warp(sr, si, e, 1, xch, tid, w, PRE && (w & 2), false); // w2  b9
    ldGate(mats + 4*12, e);  gate_lane(sr, si, e, 8, lane, PRE && (lane & 16), false);    // w4  b7
    ldGate(mats + 6*12, e);  gate_lane(sr, si, e, 2, lane, PRE && (lane & 4),  false);    // w6  b5
    ldGate(mats + 8*12, e);  tri_colswap(e, PRE && (lane & 1));                           // w8  b3
    gate_j<4, 0, 0>(sr, si, e);
    ldGate(mats + 10*12, e);                                                              // w10 b1
    if (PRE) gate_j<1, 2, 0>(sr, si, e);
    else     gate_j<1, 0, 0>(sr, si, e);
    // ---- second half: odd wires (post CNOT row swaps) ----
    ldGate(mats + 1*12, e);  gate_warp(sr, si, e, 2, xch, tid, w, false, (w & 4) != 0);   // w1  b10
    ldGate(mats + 3*12, e);  gate_lane(sr, si, e, 16, lane, false, (w & 1) != 0);         // w3  b8
    ldGate(mats + 5*12, e);  gate_lane(sr, si, e, 4, lane, false, (lane & 8) != 0);       // w5  b6
    ldGate(mats + 7*12, e);  gate_lane(sr, si, e, 1, lane, false, (lane & 2) != 0);       // w7  b4
    ldGate(mats + 9*12, e);  gate_j<2, 0, 4>(sr, si, e);                                  // w9  b2
    gate_h(sr, si, mats + 11*12);                                                         // w11 b0
}

// ---------------- main kernel ----------------
__global__ __launch_bounds__(NT, 2)
void vqc_reg_kernel(int B)
{
    __shared__ ulonglong2 xch[8 * NT];      // 32 KB exchange buffer
    __shared__ float      red[NWARP * NQ];

    const int b    = blockIdx.x;
    const int e    = blockIdx.y;
    const int tid  = threadIdx.x;
    const int lane = tid & 31;
    const int w    = tid >> 5;

    // ---- encoding: direct product-state construction ----
    const float4* col = g_em + (e * B + b) * NQ;
    float2 ph;
    {
        float4 c0 = col[0];
        ph = ((tid >> 7) & 1) ? make_float2(c0.z, c0.w) : make_float2(c0.x, c0.y);
        #pragma unroll
        for (int q = 1; q < 8; q++) {
            float4 cq = col[q];
            float2 v = ((tid >> (7 - q)) & 1) ? make_float2(cq.z, cq.w)
                                              : make_float2(cq.x, cq.y);
            ph = cmul(ph, v);
        }
    }
    u64 sr[8], si[8];
    {
        float4 c8 = col[8], c9 = col[9], c10 = col[10], c11 = col[11];
        float2 t2[2], t4[4], t8[8];
        t2[0] = cmul(ph, make_float2(c8.x, c8.y));
        t2[1] = cmul(ph, make_float2(c8.z, c8.w));
        #pragma unroll
        for (int i = 0; i < 2; i++) {
            t4[i*2+0] = cmul(t2[i], make_float2(c9.x, c9.y));
            t4[i*2+1] = cmul(t2[i], make_float2(c9.z, c9.w));
        }
        #pragma unroll
        for (int i = 0; i < 4; i++) {
            t8[i*2+0] = cmul(t4[i], make_float2(c10.x, c10.y));
            t8[i*2+1] = cmul(t4[i], make_float2(c10.z, c10.w));
        }
        #pragma unroll
        for (int j = 0; j < 8; j++) {
            float2 a  = cmul(t8[j], make_float2(c11.x, c11.y));   // h = 0
            float2 bm = cmul(t8[j], make_float2(c11.z, c11.w));   // h = 1
            sr[j] = pk2(a.x, bm.x);
            si[j] = pk2(a.y, bm.y);
        }
    }

    // ---- variational layers, CNOTs fully fused ----
    vsweepf<false>(g_vm + 0 * 12 * 12, sr, si, xch, tid, lane, w);
    vsweepf<true >(g_vm + 1 * 12 * 12, sr, si, xch, tid, lane, w);
    vsweepf<true >(g_vm + 2 * 12 * 12, sr, si, xch, tid, lane, w);
    vsweepf<true >(g_vm + 3 * 12 * 12, sr, si, xch, tid, lane, w);
    // remaining: layer-3 odd-ladder CNOTs -> folded into epilogue signs:
    //   b9^=b10, b7^=b8, b5^=b6, b3^=b4, b1^=b2

    // ---- <Z_q> for all 12 qubits (signs use permuted bits) ----
    float t[16], tot = 0.f;
    #pragma unroll
    for (int j = 0; j < 8; j++) {
        u64 p2 = pfma(si[j], si[j], pmul(sr[j], sr[j]));
        float p0, p1; upk2(p2, p0, p1);
        t[2*j] = p0; t[2*j+1] = p1;
        tot += p0 + p1;
    }
    const int t7 = (tid >> 7) & 1, t6 = (tid >> 6) & 1, t5 = (tid >> 5) & 1,
              t4b = (tid >> 4) & 1, t3 = (tid >> 3) & 1, t2b = (tid >> 2) & 1,
              t1 = (tid >> 1) & 1, t0 = tid & 1;
    float ez[NQ];
    ez[0] = t7        ? -tot : tot;   // bit 11
    ez[1] = t6        ? -tot : tot;   // bit 10
    ez[2] = (t5 ^ t6) ? -tot : tot;   // bit 9 ^ bit 10
    ez[3] = t4b       ? -tot : tot;   // bit 8
    ez[4] = (t3 ^ t4b)? -tot : tot;   // bit 7 ^ bit 8
    ez[5] = t2b       ? -tot : tot;   // bit 6
    ez[6] = (t1 ^ t2b)? -tot : tot;   // bit 5 ^ bit 6
    ez[7] = t0        ? -tot : tot;   // bit 4
    float a8 = 0.f, a9 = 0.f, a10 = 0.f, a11 = 0.f;
    #pragma unroll
    for (int k = 0; k < 16; k++) {
        a8  += (k & 8) ? -t[k] : t[k];                      // k bit 3
        a9  += (k & 4) ? -t[k] : t[k];                      // k bit 2
        a10 += (((k >> 1) ^ (k >> 2)) & 1) ? -t[k] : t[k];  // k bit1 ^ bit2
        a11 += (k & 1) ? -t[k] : t[k];                      // k bit 0
    }
    ez[8]  = t0 ? -a8 : a8;           // (bit 3 ^ bit 4); bit4 = tid bit 0
    ez[9]  = a9;
    ez[10] = a10;
    ez[11] = a11;

    #pragma unroll
    for (int q = 0; q < NQ; q++)
        #pragma unroll
        for (int o = 16; o > 0; o >>= 1)
            ez[q] += __shfl_xor_sync(0xffffffffu, ez[q], o);

    if (lane == 0) {
        #pragma unroll
        for (int q = 0; q < NQ; q++) red[w * NQ + q] = ez[q];
    }
    __syncthreads();
    if (tid < NQ) {
        float acc = 0.f;
        #pragma unroll
        for (int j = 0; j < NWARP; j++) acc += red[j * NQ + tid];
        g_branch[(e * B + b) * NQ + tid] = acc;
    }
}

// ---------------- softmax(alpha)-weighted branch mix ----------------
__global__ void reduce_kernel(const float* __restrict__ alpha,
                              float* __restrict__ out, int B)
{
    int idx = blockIdx.x * blockDim.x + threadIdx.x;
    if (idx >= B * NQ) return;
    float a0 = alpha[0], a1 = alpha[1], a2 = alpha[2], a3 = alpha[3];
    float m  = fmaxf(fmaxf(a0, a1), fmaxf(a2, a3));
    float w0 = expf(a0 - m), w1 = expf(a1 - m), w2 = expf(a2 - m), w3 = expf(a3 - m);
    float inv = 1.f / (w0 + w1 + w2 + w3);
    int stride = B * NQ;
    float y = w0 * g_branch[idx]
            + w1 * g_branch[stride + idx]
            + w2 * g_branch[2 * stride + idx]
            + w3 * g_branch[3 * stride + idx];
    out[idx] = y * inv;
}

extern "C" void kernel_launch(void* const* d_in, const int* in_sizes, int n_in,
                              void* d_out, int out_size)
{
    const float* features = (const float*)d_in[0];   // (B, 12)
    const float* theta    = (const float*)d_in[1];   // (4, 12, 3)
    const float* alpha    = (const float*)d_in[2];   // (4,)
    float* out = (float*)d_out;                      // (B, 12)

    int B = in_sizes[0] / NQ;
    if (B > MAXB) B = MAXB;

    prep_var_kernel<<<1, 64>>>(theta);
    int nenc = NENC * B * NQ;
    prep_enc_kernel<<<(nenc + 255) / 256, 256>>>(features, B);

    dim3 grid(B, NENC);
    vqc_reg_kernel<<<grid, NT>>>(B);

    int n = B * NQ;
    reduce_kernel<<<(n + 255) / 256, 256>>>(alpha, out, B);
}

// round 10
// speedup vs baseline: 3.0045x; 1.0698x over previous
#include <cuda_runtime.h>

#define NQ      12
#define NT      256
#define NWARP   8
#define LAYERS  4
#define NENC    4
#define MAXB    1024

typedef unsigned long long u64;

// ---------------- static device scratch (no allocations) ----------------
__device__ float g_branch[NENC * MAXB * NQ];
// variational gates: 12 u64 broadcast coefficients per gate (see prep)
__device__ u64   g_vm[LAYERS * 12 * 12];
// encoding: first column of R(·H) per (e,b,q): (c0.x, c0.y, c1.x, c1.y)
__device__ float4 g_em[NENC * MAXB * NQ];

// ---------------- scalar complex helpers (prep + encoding) ----------------
__device__ __forceinline__ float2 cmul(float2 a, float2 b) {
    return make_float2(fmaf(a.x, b.x, -a.y * b.y), fmaf(a.x, b.y, a.y * b.x));
}
__device__ __forceinline__ float2 cadd(float2 a, float2 b) {
    return make_float2(a.x + b.x, a.y + b.y);
}
struct M2 { float2 m00, m01, m10, m11; };
__device__ __forceinline__ M2 mmul(const M2& A, const M2& B) {
    M2 C;
    C.m00 = cadd(cmul(A.m00, B.m00), cmul(A.m01, B.m10));
    C.m01 = cadd(cmul(A.m00, B.m01), cmul(A.m01, B.m11));
    C.m10 = cadd(cmul(A.m10, B.m00), cmul(A.m11, B.m10));
    C.m11 = cadd(cmul(A.m10, B.m01), cmul(A.m11, B.m11));
    return C;
}
__device__ __forceinline__ M2 rx_m(float t) {
    float s, c; sincosf(0.5f * t, &s, &c);
    M2 M; M.m00 = {c, 0.f}; M.m01 = {0.f, -s}; M.m10 = {0.f, -s}; M.m11 = {c, 0.f};
    return M;
}
__device__ __forceinline__ M2 ry_m(float t) {
    float s, c; sincosf(0.5f * t, &s, &c);
    M2 M; M.m00 = {c, 0.f}; M.m01 = {-s, 0.f}; M.m10 = {s, 0.f}; M.m11 = {c, 0.f};
    return M;
}
__device__ __forceinline__ M2 rz_m(float t) {
    float s, c; sincosf(0.5f * t, &s, &c);
    M2 M; M.m00 = {c, -s}; M.m01 = {0.f, 0.f}; M.m10 = {0.f, 0.f}; M.m11 = {c, s};
    return M;
}

// ---------------- packed f32x2 primitives ----------------
__device__ __forceinline__ u64 pk2(float x, float y) {
    u64 r; asm("mov.b64 %0, {%1, %2};" : "=l"(r) : "f"(x), "f"(y)); return r;
}
__device__ __forceinline__ void upk2(u64 v, float& x, float& y) {
    asm("mov.b64 {%0, %1}, %2;" : "=f"(x), "=f"(y) : "l"(v));
}
__device__ __forceinline__ u64 pswap(u64 v) {           // (x,y) -> (y,x)
    float x, y; upk2(v, x, y); return pk2(y, x);
}
__device__ __forceinline__ u64 pmul(u64 a, u64 b) {
    u64 r; asm("mul.rn.f32x2 %0, %1, %2;" : "=l"(r) : "l"(a), "l"(b)); return r;
}
__device__ __forceinline__ u64 pfma(u64 a, u64 b, u64 c) {
    u64 r; asm("fma.rn.f32x2 %0, %1, %2, %3;" : "=l"(r) : "l"(a), "l"(b), "l"(c)); return r;
}
__device__ __forceinline__ u64 shfl64(u64 v, int m) {
    float x, y; upk2(v, x, y);
    x = __shfl_xor_sync(0xffffffffu, x, m);
    y = __shfl_xor_sync(0xffffffffu, y, m);
    return pk2(x, y);
}

// broadcast coefficient triple for one matrix element: (r,r), (i,i), (-i,-i)
struct Tri { u64 r, i, ni; };

__device__ __forceinline__ void ldGate(const u64* __restrict__ p, Tri e[4]) {
    const ulonglong2* v = (const ulonglong2*)p;
    ulonglong2 v0 = v[0], v1 = v[1], v2 = v[2], v3 = v[3], v4 = v[4], v5 = v[5];
    e[0].r = v0.x; e[0].i = v0.y; e[0].ni = v1.x;
    e[1].r = v1.y; e[1].i = v2.x; e[1].ni = v2.y;
    e[2].r = v3.x; e[2].i = v3.y; e[2].ni = v4.x;
    e[3].r = v4.y; e[3].i = v5.x; e[3].ni = v5.y;
}
__device__ __forceinline__ void tri_colswap(Tri e[4], bool p) {
    Tri t0 = p ? e[1] : e[0], t1 = p ? e[0] : e[1];
    Tri t2 = p ? e[3] : e[2], t3 = p ? e[2] : e[3];
    e[0] = t0; e[1] = t1; e[2] = t2; e[3] = t3;
}

// ---------------- prep kernels ----------------
__global__ void prep_var_kernel(const float* __restrict__ theta) {
    int idx = blockIdx.x * blockDim.x + threadIdx.x;        // l*NQ + q
    if (idx >= LAYERS * NQ) return;
    int q = idx % NQ;
    const float* th = theta + idx * 3;
    M2 M = mmul(rz_m(th[2]), mmul(ry_m(th[1]), rx_m(th[0])));
    u64* dst = g_vm + idx * 12;
    if (q < 11) {
        float2 el[4] = { M.m00, M.m01, M.m10, M.m11 };
        #pragma unroll
        for (int m = 0; m < 4; m++) {
            dst[m*3+0] = pk2(el[m].x, el[m].x);
            dst[m*3+1] = pk2(el[m].y, el[m].y);
            dst[m*3+2] = pk2(-el[m].y, -el[m].y);
        }
    } else {
        // wire-11 (amp bit 0, within-u64) gate: set A (even j), set B (odd j,
        // row-swapped: absorbs the post CNOT(ctrl=bit1) output swap).
        float r00 = M.m00.x, i00 = M.m00.y, r01 = M.m01.x, i01 = M.m01.y;
        float r10 = M.m10.x, i10 = M.m10.y, r11 = M.m11.x, i11 = M.m11.y;
        dst[0]  = pk2(r00, r11);  dst[1]  = pk2(r01, r10);
        dst[2]  = pk2(-i00, -i11); dst[3] = pk2(-i01, -i10);
        dst[4]  = pk2(i00, i11);  dst[5]  = pk2(i01, i10);
        dst[6]  = pk2(r10, r01);  dst[7]  = pk2(r11, r00);
        dst[8]  = pk2(-i10, -i01); dst[9] = pk2(-i11, -i00);
        dst[10] = pk2(i10, i01);  dst[11] = pk2(i11, i00);
    }
}

__global__ void prep_enc_kernel(const float* __restrict__ features, int B) {
    int idx = blockIdx.x * blockDim.x + threadIdx.x;        // e*B*NQ + b*NQ + q
    if (idx >= NENC * B * NQ) return;
    int q = idx % NQ;
    int b = (idx / NQ) % B;
    int e = idx / (B * NQ);
    float f = features[b * NQ + q];
    M2 R = (e & 1) ? ry_m(f) : rx_m(f);
    if (e >= 2) {
        const float r = 0.7071067811865476f;
        M2 H; H.m00 = {r, 0.f}; H.m01 = {r, 0.f}; H.m10 = {r, 0.f}; H.m11 = {-r, 0.f};
        R = mmul(R, H);
    }
    g_em[idx] = make_float4(R.m00.x, R.m00.y, R.m10.x, R.m10.y);
}

// ---------------- SoA register-resident gate primitives ----------------
// Layout A: amp = (w<<9) | (lane<<4) | (j<<1) | h.
// Layout B (transposed): amp bits 9-11 live in j, amp bits 1-3 in w.
// State: sr[8], si[8] (u64): (val@h=0, val@h=1) packed per f32x2.

template<int JB, int PREJ, int POSTJ>
__device__ __forceinline__ void gate_j(u64 sr[8], u64 si[8], const Tri e[4]) {
    #pragma unroll
    for (int j = 0; j < 8; j++) {
        if (!(j & JB)) {
            const int j1 = j | JB;
            const bool pre  = (PREJ != 0) && ((j & PREJ) != 0);
            const bool post = (POSTJ != 0) && ((j & POSTJ) != 0);
            const int ja = pre ? j1 : j, jb = pre ? j : j1;
            u64 Ar = sr[ja], Ai = si[ja], Br = sr[jb], Bi = si[jb];
            u64 o0r = pfma(e[1].ni, Bi, pfma(e[1].r, Br, pfma(e[0].ni, Ai, pmul(e[0].r, Ar))));
            u64 o0i = pfma(e[1].r,  Bi, pfma(e[1].i, Br, pfma(e[0].r,  Ai, pmul(e[0].i, Ar))));
            u64 o1r = pfma(e[3].ni, Bi, pfma(e[3].r, Br, pfma(e[2].ni, Ai, pmul(e[2].r, Ar))));
            u64 o1i = pfma(e[3].r,  Bi, pfma(e[3].i, Br, pfma(e[2].r,  Ai, pmul(e[2].i, Ar))));
            sr[post ? j1 : j]  = o0r; si[post ? j1 : j]  = o0i;
            sr[post ? j : j1]  = o1r; si[post ? j : j1]  = o1i;
        }
    }
}

__device__ __forceinline__ void pick_pq(const Tri e[4], bool hi, bool cswap, bool rxor,
                                        Tri& P, Tri& Q) {
    const bool row = hi ^ rxor, cs = hi ^ cswap;
    Tri r0 = row ? e[2] : e[0];
    Tri r1 = row ? e[3] : e[1];
    P = cs ? r1 : r0;
    Q = cs ? r0 : r1;
}

__device__ __forceinline__ void gate_lane(u64 sr[8], u64 si[8], const Tri e[4],
                                          int mask, int lane, bool cswap, bool rxor) {
    const bool hi = (lane & mask) != 0;
    Tri P, Q; pick_pq(e, hi, cswap, rxor, P, Q);
    #pragma unroll
    for (int j = 0; j < 8; j++) {
        u64 orr = shfl64(sr[j], mask);
        u64 oii = shfl64(si[j], mask);
        u64 nr = pfma(Q.ni, oii, pfma(Q.r, orr, pfma(P.ni, si[j], pmul(P.r, sr[j]))));
        u64 nm = pfma(Q.r,  oii, pfma(Q.i, orr, pfma(P.r,  si[j], pmul(P.i, sr[j]))));
        sr[j] = nr; si[j] = nm;
    }
}

// wire-11 gate on amp bit 0 (within-u64), post CNOT(ctrl=bit1) fused.
__device__ __forceinline__ void gate_h(u64 sr[8], u64 si[8], const u64* __restrict__ cp) {
    u64 c[12];
    const ulonglong2* v = (const ulonglong2*)cp;
    #pragma unroll
    for (int m = 0; m < 6; m++) { ulonglong2 t = v[m]; c[2*m] = t.x; c[2*m+1] = t.y; }
    #pragma unroll
    for (int j = 0; j < 8; j++) {
        const int o = (j & 1) ? 6 : 0;
        u64 rd = c[o+0], rs = c[o+1], nid = c[o+2], nis = c[o+3], id = c[o+4], is = c[o+5];
        u64 swr = pswap(sr[j]), swi = pswap(si[j]);
        u64 nr = pfma(nis, swi, pfma(nid, si[j], pfma(rs, swr, pmul(rd, sr[j]))));
        u64 nm = pfma(rs,  swi, pfma(rd,  si[j], pfma(is, swr, pmul(id, sr[j]))));
        sr[j] = nr; si[j] = nm;
    }
}

// ---------------- layout transpose: amp bits 1-3 <-> 9-11 ----------------
// Bank-conflict-free via phys = u ^ ((u>>3)&7) = u ^ (lane&7).
// HIGHSTORE=false: store A-layout indices, load B-layout (A -> B).
// HIGHSTORE=true : store B-layout indices, load A-layout (B -> A).
template<bool HIGHSTORE>
__device__ __forceinline__ void transpose3(u64 sr[8], u64 si[8],
                                           ulonglong2* __restrict__ buf,
                                           int lane, int w) {
    #pragma unroll
    for (int j = 0; j < 8; j++) {
        int u = HIGHSTORE ? ((j << 8) | (lane << 3) | w)
                          : ((w << 8) | (lane << 3) | j);
        buf[u ^ (lane & 7)] = make_ulonglong2(sr[j], si[j]);
    }
    __syncthreads();
    #pragma unroll
    for (int j = 0; j < 8; j++) {
        int u = HIGHSTORE ? ((w << 8) | (lane << 3) | j)
                          : ((j << 8) | (lane << 3) | w);
        ulonglong2 v = buf[u ^ (lane & 7)];
        sr[j] = v.x; si[j] = v.y;
    }
}

// Fused sweep. Phase B (transposed: bits 9-11 local): wires 0,2,1 with
// compile-time CNOT predicates. Phase A: evens b7,b5,b3,b1 (pre col swaps,
// prev layer odd ladder) then odds b8,b6,b4,b2,b0 (post row swaps, this
// layer's even ladder). This layer's odd ladder defers onward.
template<bool PRE>
__device__ __forceinline__ void vsweepf(const u64* __restrict__ mats,
                                        u64 sr[8], u64 si[8],
                                        ulonglong2* bufAB, ulonglong2* bufBA,
                                        int lane, int w) {
    Tri e[4];
    // ---- phase B: transposed, bits 9-11 are j bits 0-2 ----
    transpose3<false>(sr, si, bufAB, lane, w);
    ldGate(mats + 0*12, e);  gate_j<4, 0, 0>(sr, si, e);           // w0  b11
    ldGate(mats + 2*12, e);                                        // w2  b9, pre c=b10 (j bit 1)
    if (PRE) gate_j<1, 2, 0>(sr, si, e);
    else     gate_j<1, 0, 0>(sr, si, e);
    ldGate(mats + 1*12, e);  gate_j<2, 0, 4>(sr, si, e);           // w1  b10, post c=b11 (j bit 2)
    transpose3<true>(sr, si, bufBA, lane, w);
    // ---- phase A evens ----
    ldGate(mats + 4*12, e);  gate_lane(sr, si, e, 8, lane, PRE && (lane & 16), false); // w4 b7
    ldGate(mats + 6*12, e);  gate_lane(sr, si, e, 2, lane, PRE && (lane & 4),  false); // w6 b5
    ldGate(mats + 8*12, e);  tri_colswap(e, PRE && (lane & 1));                        // w8 b3
    gate_j<4, 0, 0>(sr, si, e);
    ldGate(mats + 10*12, e);                                                           // w10 b1
    if (PRE) gate_j<1, 2, 0>(sr, si, e);
    else     gate_j<1, 0, 0>(sr, si, e);
    // ---- phase A odds (post row swaps) ----
    ldGate(mats + 3*12, e);  gate_lane(sr, si, e, 16, lane, false, (w & 1) != 0);      // w3 b8
    ldGate(mats + 5*12, e);  gate_lane(sr, si, e, 4, lane, false, (lane & 8) != 0);    // w5 b6
    ldGate(mats + 7*12, e);  gate_lane(sr, si, e, 1, lane, false, (lane & 2) != 0);    // w7 b4
    ldGate(mats + 9*12, e);  gate_j<2, 0, 4>(sr, si, e);                               // w9 b2
    gate_h(sr, si, mats + 11*12);                                                      // w11 b0
}

// ---------------- main kernel ----------------
__global__ __launch_bounds__(NT, 2)
void vqc_reg_kernel(int B)
{
    extern __shared__ ulonglong2 dynbuf[];   // [0..2047] bufAB, [2048..4095] bufBA
    __shared__ float red[NWARP * NQ];
    ulonglong2* bufAB = dynbuf;
    ulonglong2* bufBA = dynbuf + 2048;

    const int b    = blockIdx.x;
    const int e    = blockIdx.y;
    const int tid  = threadIdx.x;
    const int lane = tid & 31;
    const int w    = tid >> 5;

    // ---- encoding: direct product-state construction (layout A) ----
    const float4* col = g_em + (e * B + b) * NQ;
    float2 ph;
    {
        float4 c0 = col[0];
        ph = ((tid >> 7) & 1) ? make_float2(c0.z, c0.w) : make_float2(c0.x, c0.y);
        #pragma unroll
        for (int q = 1; q < 8; q++) {
            float4 cq = col[q];
            float2 v = ((tid >> (7 - q)) & 1) ? make_float2(cq.z, cq.w)
                                              : make_float2(cq.x, cq.y);
            ph = cmul(ph, v);
        }
    }
    u64 sr[8], si[8];
    {
        float4 c8 = col[8], c9 = col[9], c10 = col[10], c11 = col[11];
        float2 t2[2], t4[4], t8[8];
        t2[0] = cmul(ph, make_float2(c8.x, c8.y));
        t2[1] = cmul(ph, make_float2(c8.z, c8.w));
        #pragma unroll
        for (int i = 0; i < 2; i++) {
            t4[i*2+0] = cmul(t2[i], make_float2(c9.x, c9.y));
            t4[i*2+1] = cmul(t2[i], make_float2(c9.z, c9.w));
        }
        #pragma unroll
        for (int i = 0; i < 4; i++) {
            t8[i*2+0] = cmul(t4[i], make_float2(c10.x, c10.y));
            t8[i*2+1] = cmul(t4[i], make_float2(c10.z, c10.w));
        }
        #pragma unroll
        for (int j = 0; j < 8; j++) {
            float2 a  = cmul(t8[j], make_float2(c11.x, c11.y));   // h = 0
            float2 bm = cmul(t8[j], make_float2(c11.z, c11.w));   // h = 1
            sr[j] = pk2(a.x, bm.x);
            si[j] = pk2(a.y, bm.y);
        }
    }

    // ---- variational layers, CNOTs fully fused ----
    vsweepf<false>(g_vm + 0 * 12 * 12, sr, si, bufAB, bufBA, lane, w);
    vsweepf<true >(g_vm + 1 * 12 * 12, sr, si, bufAB, bufBA, lane, w);
    vsweepf<true >(g_vm + 2 * 12 * 12, sr, si, bufAB, bufBA, lane, w);
    vsweepf<true >(g_vm + 3 * 12 * 12, sr, si, bufAB, bufBA, lane, w);
    // remaining: layer-3 odd-ladder CNOTs -> folded into epilogue signs:
    //   b9^=b10, b7^=b8, b5^=b6, b3^=b4, b1^=b2

    // ---- <Z_q> for all 12 qubits (signs use permuted bits) ----
    float t[16], tot = 0.f;
    #pragma unroll
    for (int j = 0; j < 8; j++) {
        u64 p2 = pfma(si[j], si[j], pmul(sr[j], sr[j]));
        float p0, p1; upk2(p2, p0, p1);
        t[2*j] = p0; t[2*j+1] = p1;
        tot += p0 + p1;
    }
    const int t7 = (tid >> 7) & 1, t6 = (tid >> 6) & 1, t5 = (tid >> 5) & 1,
              t4b = (tid >> 4) & 1, t3 = (tid >> 3) & 1, t2b = (tid >> 2) & 1,
              t1 = (tid >> 1) & 1, t0 = tid & 1;
    float ez[NQ];
    ez[0] = t7        ? -tot : tot;   // bit 11
    ez[1] = t6        ? -tot : tot;   // bit 10
    ez[2] = (t5 ^ t6) ? -tot : tot;   // bit 9 ^ bit 10
    ez[3] = t4b       ? -tot : tot;   // bit 8
    ez[4] = (t3 ^ t4b)? -tot : tot;   // bit 7 ^ bit 8
    ez[5] = t2b       ? -tot : tot;   // bit 6
    ez[6] = (t1 ^ t2b)? -tot : tot;   // bit 5 ^ bit 6
    ez[7] = t0        ? -tot : tot;   // bit 4
    float a8 = 0.f, a9 = 0.f, a10 = 0.f, a11 = 0.f;
    #pragma unroll
    for (int k = 0; k < 16; k++) {
        a8  += (k & 8) ? -t[k] : t[k];                      // k bit 3
        a9  += (k & 4) ? -t[k] : t[k];                      // k bit 2
        a10 += (((k >> 1) ^ (k >> 2)) & 1) ? -t[k] : t[k];  // k bit1 ^ bit2
        a11 += (k & 1) ? -t[k] : t[k];                      // k bit 0
    }
    ez[8]  = t0 ? -a8 : a8;           // (bit 3 ^ bit 4); bit4 = tid bit 0
    ez[9]  = a9;
    ez[10] = a10;
    ez[11] = a11;

    #pragma unroll
    for (int q = 0; q < NQ; q++)
        #pragma unroll
        for (int o = 16; o > 0; o >>= 1)
            ez[q] += __shfl_xor_sync(0xffffffffu, ez[q], o);

    if (lane == 0) {
        #pragma unroll
        for (int q = 0; q < NQ; q++) red[w * NQ + q] = ez[q];
    }
    __syncthreads();
    if (tid < NQ) {
        float acc = 0.f;
        #pragma unroll
        for (int j = 0; j < NWARP; j++) acc += red[j * NQ + tid];
        g_branch[(e * B + b) * NQ + tid] = acc;
    }
}

// ---------------- softmax(alpha)-weighted branch mix ----------------
__global__ void reduce_kernel(const float* __restrict__ alpha,
                              float* __restrict__ out, int B)
{
    int idx = blockIdx.x * blockDim.x + threadIdx.x;
    if (idx >= B * NQ) return;
    float a0 = alpha[0], a1 = alpha[1], a2 = alpha[2], a3 = alpha[3];
    float m  = fmaxf(fmaxf(a0, a1), fmaxf(a2, a3));
    float w0 = expf(a0 - m), w1 = expf(a1 - m), w2 = expf(a2 - m), w3 = expf(a3 - m);
    float inv = 1.f / (w0 + w1 + w2 + w3);
    int stride = B * NQ;
    float y = w0 * g_branch[idx]
            + w1 * g_branch[stride + idx]
            + w2 * g_branch[2 * stride + idx]
            + w3 * g_branch[3 * stride + idx];
    out[idx] = y * inv;
}

extern "C" void kernel_launch(void* const* d_in, const int* in_sizes, int n_in,
                              void* d_out, int out_size)
{
    const float* features = (const float*)d_in[0];   // (B, 12)
    const float* theta    = (const float*)d_in[1];   // (4, 12, 3)
    const float* alpha    = (const float*)d_in[2];   // (4,)
    float* out = (float*)d_out;                      // (B, 12)

    int B = in_sizes[0] / NQ;
    if (B > MAXB) B = MAXB;

    const int SMEM_DYN = 4096 * (int)sizeof(ulonglong2);   // 64 KB double buffer
    cudaFuncSetAttribute(vqc_reg_kernel,
                         cudaFuncAttributeMaxDynamicSharedMemorySize, SMEM_DYN);

    prep_var_kernel<<<1, 64>>>(theta);
    int nenc = NENC * B * NQ;
    prep_enc_kernel<<<(nenc + 255) / 256, 256>>>(features, B);

    dim3 grid(B, NENC);
    vqc_reg_kernel<<<grid, NT, SMEM_DYN>>>(B);

    int n = B * NQ;
    reduce_kernel<<<(n + 255) / 256, 256>>>(alpha, out, B);
}

// round 11
// speedup vs baseline: 4.6068x; 1.5333x over previous
#include <cuda_runtime.h>

#define NQ      12
#define NT      256
#define NWARP   8
#define LAYERS  4
#define NENC    4
#define MAXB    1024

typedef unsigned long long u64;

// ---------------- static device scratch (no allocations) ----------------
__device__ float g_branch[NENC * MAXB * NQ];
// real-Y gate coefficients: per (l,q) 4 u64. q<11: [ (c,c), (s,s), 0, 0 ].
// q=11 (amp bit 0, within-u64): [ dA=(c,c), oA=(-s,s), dB=(s,-s), oB=(c,c) ].
__device__ u64   g_vry[LAYERS * NQ * 4];
// ZYZ diagonal angles per (l,q)
__device__ float g_alpha[LAYERS * NQ];
__device__ float g_gamma[LAYERS * NQ];
// boundary diagonals (theta-only, shared by all CTAs):
// 3 boundaries x 2048 amp-pairs: { (r_h0,r_h1), (i_h0,i_h1) },
// slot = (j<<8) | (w<<5) | lane  for amp pair xp=(w<<8)|(lane<<3)|j
__device__ ulonglong2 g_diag[3 * 2048];
// encoding columns (gamma_1 folded): (c0.x, c0.y, c1.x, c1.y)
__device__ float4 g_em[NENC * MAXB * NQ];

// ---------------- scalar complex helpers (prep + encoding) ----------------
__device__ __forceinline__ float2 cmul(float2 a, float2 b) {
    return make_float2(fmaf(a.x, b.x, -a.y * b.y), fmaf(a.x, b.y, a.y * b.x));
}
__device__ __forceinline__ float2 cadd(float2 a, float2 b) {
    return make_float2(a.x + b.x, a.y + b.y);
}
struct M2 { float2 m00, m01, m10, m11; };
__device__ __forceinline__ M2 mmul(const M2& A, const M2& B) {
    M2 C;
    C.m00 = cadd(cmul(A.m00, B.m00), cmul(A.m01, B.m10));
    C.m01 = cadd(cmul(A.m00, B.m01), cmul(A.m01, B.m11));
    C.m10 = cadd(cmul(A.m10, B.m00), cmul(A.m11, B.m10));
    C.m11 = cadd(cmul(A.m10, B.m01), cmul(A.m11, B.m11));
    return C;
}
__device__ __forceinline__ M2 rx_m(float t) {
    float s, c; sincosf(0.5f * t, &s, &c);
    M2 M; M.m00 = {c, 0.f}; M.m01 = {0.f, -s}; M.m10 = {0.f, -s}; M.m11 = {c, 0.f};
    return M;
}
__device__ __forceinline__ M2 ry_m(float t) {
    float s, c; sincosf(0.5f * t, &s, &c);
    M2 M; M.m00 = {c, 0.f}; M.m01 = {-s, 0.f}; M.m10 = {s, 0.f}; M.m11 = {c, 0.f};
    return M;
}
__device__ __forceinline__ M2 rz_m(float t) {
    float s, c; sincosf(0.5f * t, &s, &c);
    M2 M; M.m00 = {c, -s}; M.m01 = {0.f, 0.f}; M.m10 = {0.f, 0.f}; M.m11 = {c, s};
    return M;
}

// ---------------- packed f32x2 primitives ----------------
__device__ __forceinline__ u64 pk2(float x, float y) {
    u64 r; asm("mov.b64 %0, {%1, %2};" : "=l"(r) : "f"(x), "f"(y)); return r;
}
__device__ __forceinline__ void upk2(u64 v, float& x, float& y) {
    asm("mov.b64 {%0, %1}, %2;" : "=f"(x), "=f"(y) : "l"(v));
}
__device__ __forceinline__ u64 pswap(u64 v) {           // (x,y) -> (y,x)
    float x, y; upk2(v, x, y); return pk2(y, x);
}
__device__ __forceinline__ u64 pmul(u64 a, u64 b) {
    u64 r; asm("mul.rn.f32x2 %0, %1, %2;" : "=l"(r) : "l"(a), "l"(b)); return r;
}
__device__ __forceinline__ u64 pfma(u64 a, u64 b, u64 c) {
    u64 r; asm("fma.rn.f32x2 %0, %1, %2, %3;" : "=l"(r) : "l"(a), "l"(b), "l"(c)); return r;
}
__device__ __forceinline__ u64 shfl64(u64 v, int m) {
    float x, y; upk2(v, x, y);
    x = __shfl_xor_sync(0xffffffffu, x, m);
    y = __shfl_xor_sync(0xffffffffu, y, m);
    return pk2(x, y);
}

#define SIGNMASK 0x8000000080000000ULL

// ---------------- prep kernels ----------------
// ZYZ: M = RZ(alpha) RY(beta) RZ(gamma), M in SU(2):
//   m00 = c e^{-i(a+g)/2}, m10 = s e^{i(a-g)/2}  (c,s >= 0)
//   c=|m00|, s=|m10|, p00=arg(m00), p10=arg(m10): a = p10-p00, g = -p10-p00.
__global__ void prep_var_kernel(const float* __restrict__ theta) {
    int idx = blockIdx.x * blockDim.x + threadIdx.x;        // l*NQ + q
    if (idx >= LAYERS * NQ) return;
    int q = idx % NQ;
    const float* th = theta + idx * 3;
    M2 M = mmul(rz_m(th[2]), mmul(ry_m(th[1]), rx_m(th[0])));
    float c = sqrtf(fmaf(M.m00.x, M.m00.x, M.m00.y * M.m00.y));
    float s = sqrtf(fmaf(M.m10.x, M.m10.x, M.m10.y * M.m10.y));
    float p00 = atan2f(M.m00.y, M.m00.x);
    float p10 = atan2f(M.m10.y, M.m10.x);
    g_alpha[idx] = p10 - p00;
    g_gamma[idx] = -p10 - p00;
    u64* dst = g_vry + idx * 4;
    if (q < 11) {
        dst[0] = pk2(c, c); dst[1] = pk2(s, s);
        dst[2] = 0; dst[3] = 0;
    } else {
        dst[0] = pk2(c, c);   dst[1] = pk2(-s, s);    // set A (even j)
        dst[2] = pk2(s, -s);  dst[3] = pk2(c, c);     // set B (odd j, row-swapped)
    }
}

// boundary diagonal l (after layer l+1's even+odd ladders, physical coords):
//   delta_l(x) = d_alpha[l](Ce x) * d_gamma[l+1](Co x)
//   Ce: b_{p} ^= b_{p+1} for p in {0,2,4,6,8,10};  Co: p in {1,3,5,7,9}
__global__ void prep_diag_kernel() {
    int idx = blockIdx.x * blockDim.x + threadIdx.x;
    if (idx >= 3 * 2048) return;
    int l    = idx >> 11;
    int slot = idx & 2047;
    int j    = (slot >> 8) & 7;
    int w    = (slot >> 5) & 7;
    int lane = slot & 31;
    int xp   = (w << 8) | (lane << 3) | j;
    const float* al = g_alpha + l * NQ;
    const float* gm = g_gamma + (l + 1) * NQ;
    float rr[2], ii[2];
    #pragma unroll
    for (int h = 0; h < 2; h++) {
        int x  = (xp << 1) | h;
        int ye = x ^ ((x >> 1) & 0x555);
        int yo = x ^ ((x >> 1) & 0x2AA);
        float ang = 0.f;
        for (int q = 0; q < NQ; q++) {
            int p = 11 - q;
            ang += ((ye >> p) & 1) ? 0.5f * al[q] : -0.5f * al[q];
            ang += ((yo >> p) & 1) ? 0.5f * gm[q] : -0.5f * gm[q];
        }
        float sn, cs; sincosf(ang, &sn, &cs);
        rr[h] = cs; ii[h] = sn;
    }
    g_diag[idx] = make_ulonglong2(pk2(rr[0], rr[1]), pk2(ii[0], ii[1]));
}

__global__ void prep_enc_kernel(const float* __restrict__ features, int B) {
    int idx = blockIdx.x * blockDim.x + threadIdx.x;        // e*B*NQ + b*NQ + q
    if (idx >= NENC * B * NQ) return;
    int q = idx % NQ;
    int b = (idx / NQ) % B;
    int e = idx / (B * NQ);
    float f = features[b * NQ + q];
    M2 R = (e & 1) ? ry_m(f) : rx_m(f);
    if (e >= 2) {
        const float r = 0.7071067811865476f;
        M2 H; H.m00 = {r, 0.f}; H.m01 = {r, 0.f}; H.m10 = {r, 0.f}; H.m11 = {-r, 0.f};
        R = mmul(R, H);
    }
    // fold layer-1 gamma diagonal into the encoding column
    float g = g_gamma[q];          // layer index 0
    float sg, cg; sincosf(0.5f * g, &sg, &cg);
    float2 c0 = cmul(make_float2(R.m00.x, R.m00.y), make_float2(cg, -sg));
    float2 c1 = cmul(make_float2(R.m10.x, R.m10.y), make_float2(cg, sg));
    g_em[idx] = make_float4(c0.x, c0.y, c1.x, c1.y);
}

// ---------------- real-rotation gate primitives ----------------
// Layout A: amp = (w<<9)|(lane<<4)|(j<<1)|h. Layout B (transposed): amp bits
// 9-11 in j, bits 1-3 in w. sr[j]/si[j] hold (h=0, h=1) packed per f32x2.

__device__ __forceinline__ void ldRG(const u64* __restrict__ p, u64& c, u64& s) {
    ulonglong2 v = *(const ulonglong2*)p;
    c = v.x; s = v.y;
}

// real gate: o0 = P00*A + P01*B ; o1 = P10*A + P11*B  (normal: c,-s,s,c)
template<int JB, int PREJ, int POSTJ>
__device__ __forceinline__ void gate_jr(u64 sr[8], u64 si[8],
                                        u64 P00, u64 P01, u64 P10, u64 P11) {
    #pragma unroll
    for (int j = 0; j < 8; j++) {
        if (!(j & JB)) {
            const int j1 = j | JB;
            const bool pre  = (PREJ != 0) && ((j & PREJ) != 0);
            const bool post = (POSTJ != 0) && ((j & POSTJ) != 0);
            const int ja = pre ? j1 : j, jb = pre ? j : j1;
            u64 Ar = sr[ja], Ai = si[ja], Br = sr[jb], Bi = si[jb];
            u64 o0r = pfma(P01, Br, pmul(P00, Ar));
            u64 o0i = pfma(P01, Bi, pmul(P00, Ai));
            u64 o1r = pfma(P11, Br, pmul(P10, Ar));
            u64 o1i = pfma(P11, Bi, pmul(P10, Ai));
            sr[post ? j1 : j] = o0r; si[post ? j1 : j] = o0i;
            sr[post ? j : j1] = o1r; si[post ? j : j1] = o1i;
        }
    }
}

// lane-bit real gate; coefficient-folded selects (row = hi^rxor, col = hi^cswap)
__device__ __forceinline__ void gate_laner(u64 sr[8], u64 si[8], u64 c, u64 s,
                                           int mask, int lane, bool cswap, bool rxor) {
    u64 ns = s ^ SIGNMASK;
    const bool hi   = (lane & mask) != 0;
    const bool row  = hi ^ rxor;
    const bool scol = hi ^ cswap;
    u64 sgn = row ? s : ns;
    u64 P = (row == scol) ? c : sgn;
    u64 Q = (row == scol) ? sgn : c;
    #pragma unroll
    for (int j = 0; j < 8; j++) {
        u64 orr = shfl64(sr[j], mask);
        u64 oii = shfl64(si[j], mask);
        sr[j] = pfma(Q, orr, pmul(P, sr[j]));
        si[j] = pfma(Q, oii, pmul(P, si[j]));
    }
}

// wire-11 gate on amp bit 0 (within-u64); post CNOT(ctrl=b1) fused via set B
__device__ __forceinline__ void gate_hr(u64 sr[8], u64 si[8], const u64* __restrict__ p) {
    ulonglong2 a = ((const ulonglong2*)p)[0];
    ulonglong2 b = ((const ulonglong2*)p)[1];
    #pragma unroll
    for (int j = 0; j < 8; j++) {
        u64 d = (j & 1) ? b.x : a.x;
        u64 o = (j & 1) ? b.y : a.y;
        sr[j] = pfma(o, pswap(sr[j]), pmul(d, sr[j]));
        si[j] = pfma(o, pswap(si[j]), pmul(d, si[j]));
    }
}

// boundary diagonal: per-amp complex multiply (state in layout A)
__device__ __forceinline__ void apply_diag(u64 sr[8], u64 si[8],
                                           const ulonglong2* __restrict__ tab, int tid) {
    #pragma unroll
    for (int j = 0; j < 8; j++) {
        ulonglong2 v = tab[(j << 8) | tid];
        u64 dr = v.x, di = v.y, dni = di ^ SIGNMASK;
        u64 nr = pfma(dni, si[j], pmul(dr, sr[j]));
        u64 ni = pfma(dr,  si[j], pmul(di, sr[j]));
        sr[j] = nr; si[j] = ni;
    }
}

// ---------------- layout transpose: amp bits 1-3 <-> 9-11 ----------------
template<bool HIGHSTORE>
__device__ __forceinline__ void transpose3(u64 sr[8], u64 si[8],
                                           ulonglong2* __restrict__ buf,
                                           int lane, int w) {
    #pragma unroll
    for (int j = 0; j < 8; j++) {
        int u = HIGHSTORE ? ((j << 8) | (lane << 3) | w)
                          : ((w << 8) | (lane << 3) | j);
        buf[u ^ (lane & 7)] = make_ulonglong2(sr[j], si[j]);
    }
    __syncthreads();
    #pragma unroll
    for (int j = 0; j < 8; j++) {
        int u = HIGHSTORE ? ((w << 8) | (lane << 3) | j)
                          : ((j << 8) | (lane << 3) | w);
        ulonglong2 v = buf[u ^ (lane & 7)];
        sr[j] = v.x; si[j] = v.y;
    }
}

// Fused real-rotation sweep (R9 skeleton, halved math).
template<bool PRE>
__device__ __forceinline__ void vsweepr(const u64* __restrict__ m,
                                        u64 sr[8], u64 si[8],
                                        ulonglong2* bufAB, ulonglong2* bufBA,
                                        int lane, int w) {
    u64 c, s, ns;
    // ---- phase B: transposed, amp bits 9-11 = j bits 0-2 ----
    transpose3<false>(sr, si, bufAB, lane, w);
    ldRG(m + 0*4, c, s); ns = s ^ SIGNMASK;
    gate_jr<4, 0, 0>(sr, si, c, ns, s, c);                      // b11
    ldRG(m + 2*4, c, s); ns = s ^ SIGNMASK;                     // b9, pre c=b10 (j bit1)
    if (PRE) gate_jr<1, 2, 0>(sr, si, c, ns, s, c);
    else     gate_jr<1, 0, 0>(sr, si, c, ns, s, c);
    ldRG(m + 1*4, c, s); ns = s ^ SIGNMASK;
    gate_jr<2, 0, 4>(sr, si, c, ns, s, c);                      // b10, post c=b11 (j bit2)
    transpose3<true>(sr, si, bufBA, lane, w);
    // ---- phase A evens (pre col swaps = prev layer odd ladder) ----
    ldRG(m + 4*4, c, s);
    gate_laner(sr, si, c, s, 8, lane, PRE && (lane & 16), false);   // b7, pre c=b8
    ldRG(m + 6*4, c, s);
    gate_laner(sr, si, c, s, 2, lane, PRE && (lane & 4), false);    // b5, pre c=b6
    ldRG(m + 8*4, c, s); ns = s ^ SIGNMASK;                         // b3, pre c=b4 (lane bit0)
    {
        bool cs3 = PRE && (lane & 1);
        u64 q00 = cs3 ? ns : c, q01 = cs3 ? c : ns;
        u64 q10 = cs3 ? c : s,  q11 = cs3 ? s : c;
        gate_jr<4, 0, 0>(sr, si, q00, q01, q10, q11);
    }
    ldRG(m + 10*4, c, s); ns = s ^ SIGNMASK;                        // b1, pre c=b2 (j bit1)
    if (PRE) gate_jr<1, 2, 0>(sr, si, c, ns, s, c);
    else     gate_jr<1, 0, 0>(sr, si, c, ns, s, c);
    // ---- phase A odds (post row swaps = this layer even ladder) ----
    ldRG(m + 3*4, c, s);
    gate_laner(sr, si, c, s, 16, lane, false, (w & 1) != 0);        // b8, post c=b9
    ldRG(m + 5*4, c, s);
    gate_laner(sr, si, c, s, 4, lane, false, (lane & 8) != 0);      // b6, post c=b7
    ldRG(m + 7*4, c, s);
    gate_laner(sr, si, c, s, 1, lane, false, (lane & 2) != 0);      // b4, post c=b5
    ldRG(m + 9*4, c, s); ns = s ^ SIGNMASK;
    gate_jr<2, 0, 4>(sr, si, c, ns, s, c);                          // b2, post c=b3 (j bit2)
    gate_hr(sr, si, m + 11*4);                                      // b0, post c=b1 fused
}

// ---------------- main kernel ----------------
__global__ __launch_bounds__(NT, 2)
void vqc_reg_kernel(int B)
{
    extern __shared__ ulonglong2 dynbuf[];   // [0..2047] bufAB, [2048..4095] bufBA
    __shared__ float red[NWARP * NQ];
    ulonglong2* bufAB = dynbuf;
    ulonglong2* bufBA = dynbuf + 2048;

    const int b    = blockIdx.x;
    const int e    = blockIdx.y;
    const int tid  = threadIdx.x;
    const int lane = tid & 31;
    const int w    = tid >> 5;

    // ---- encoding: direct product-state construction (gamma_1 pre-folded) ----
    const float4* col = g_em + (e * B + b) * NQ;
    float2 ph;
    {
        float4 c0 = col[0];
        ph = ((tid >> 7) & 1) ? make_float2(c0.z, c0.w) : make_float2(c0.x, c0.y);
        #pragma unroll
        for (int q = 1; q < 8; q++) {
            float4 cq = col[q];
            float2 v = ((tid >> (7 - q)) & 1) ? make_float2(cq.z, cq.w)
                                              : make_float2(cq.x, cq.y);
            ph = cmul(ph, v);
        }
    }
    u64 sr[8], si[8];
    {
        float4 c8 = col[8], c9 = col[9], c10 = col[10], c11 = col[11];
        float2 t2[2], t4[4], t8[8];
        t2[0] = cmul(ph, make_float2(c8.x, c8.y));
        t2[1] = cmul(ph, make_float2(c8.z, c8.w));
        #pragma unroll
        for (int i = 0; i < 2; i++) {
            t4[i*2+0] = cmul(t2[i], make_float2(c9.x, c9.y));
            t4[i*2+1] = cmul(t2[i], make_float2(c9.z, c9.w));
        }
        #pragma unroll
        for (int i = 0; i < 4; i++) {
            t8[i*2+0] = cmul(t4[i], make_float2(c10.x, c10.y));
            t8[i*2+1] = cmul(t4[i], make_float2(c10.z, c10.w));
        }
        #pragma unroll
        for (int j = 0; j < 8; j++) {
            float2 a  = cmul(t8[j], make_float2(c11.x, c11.y));   // h = 0
            float2 bm = cmul(t8[j], make_float2(c11.z, c11.w));   // h = 1
            sr[j] = pk2(a.x, bm.x);
            si[j] = pk2(a.y, bm.y);
        }
    }

    // ---- variational layers: real-Y sweeps + boundary diagonals ----
    vsweepr<false>(g_vry + 0 * NQ * 4, sr, si, bufAB, bufBA, lane, w);
    apply_diag(sr, si, g_diag + 0 * 2048, tid);
    vsweepr<true >(g_vry + 1 * NQ * 4, sr, si, bufAB, bufBA, lane, w);
    apply_diag(sr, si, g_diag + 1 * 2048, tid);
    vsweepr<true >(g_vry + 2 * NQ * 4, sr, si, bufAB, bufBA, lane, w);
    apply_diag(sr, si, g_diag + 2 * 2048, tid);
    vsweepr<true >(g_vry + 3 * NQ * 4, sr, si, bufAB, bufBA, lane, w);
    // alpha_4 diagonal drops at measurement; layer-4 odd ladder -> epilogue
    // sign permutation: b9^=b10, b7^=b8, b5^=b6, b3^=b4, b1^=b2

    // ---- <Z_q> for all 12 qubits (signs use permuted bits) ----
    float t[16], tot = 0.f;
    #pragma unroll
    for (int j = 0; j < 8; j++) {
        u64 p2 = pfma(si[j], si[j], pmul(sr[j], sr[j]));
        float p0, p1; upk2(p2, p0, p1);
        t[2*j] = p0; t[2*j+1] = p1;
        tot += p0 + p1;
    }
    const int t7 = (tid >> 7) & 1, t6 = (tid >> 6) & 1, t5 = (tid >> 5) & 1,
              t4b = (tid >> 4) & 1, t3 = (tid >> 3) & 1, t2b = (tid >> 2) & 1,
              t1 = (tid >> 1) & 1, t0 = tid & 1;
    float ez[NQ];
    ez[0] = t7        ? -tot : tot;   // bit 11
    ez[1] = t6        ? -tot : tot;   // bit 10
    ez[2] = (t5 ^ t6) ? -tot : tot;   // bit 9 ^ bit 10
    ez[3] = t4b       ? -tot : tot;   // bit 8
    ez[4] = (t3 ^ t4b)? -tot : tot;   // bit 7 ^ bit 8
    ez[5] = t2b       ? -tot : tot;   // bit 6
    ez[6] = (t1 ^ t2b)? -tot : tot;   // bit 5 ^ bit 6
    ez[7] = t0        ? -tot : tot;   // bit 4
    float a8 = 0.f, a9 = 0.f, a10 = 0.f, a11 = 0.f;
    #pragma unroll
    for (int k = 0; k < 16; k++) {
        a8  += (k & 8) ? -t[k] : t[k];                      // k bit 3
        a9  += (k & 4) ? -t[k] : t[k];                      // k bit 2
        a10 += (((k >> 1) ^ (k >> 2)) & 1) ? -t[k] : t[k];  // k bit1 ^ bit2
        a11 += (k & 1) ? -t[k] : t[k];                      // k bit 0
    }
    ez[8]  = t0 ? -a8 : a8;           // (bit 3 ^ bit 4); bit4 = tid bit 0
    ez[9]  = a9;
    ez[10] = a10;
    ez[11] = a11;

    #pragma unroll
    for (int q = 0; q < NQ; q++)
        #pragma unroll
        for (int o = 16; o > 0; o >>= 1)
            ez[q] += __shfl_xor_sync(0xffffffffu, ez[q], o);

    if (lane == 0) {
        #pragma unroll
        for (int q = 0; q < NQ; q++) red[w * NQ + q] = ez[q];
    }
    __syncthreads();
    if (tid < NQ) {
        float acc = 0.f;
        #pragma unroll
        for (int j = 0; j < NWARP; j++) acc += red[j * NQ + tid];
        g_branch[(e * B + b) * NQ + tid] = acc;
    }
}

// ---------------- softmax(alpha)-weighted branch mix ----------------
__global__ void reduce_kernel(const float* __restrict__ alpha,
                              float* __restrict__ out, int B)
{
    int idx = blockIdx.x * blockDim.x + threadIdx.x;
    if (idx >= B * NQ) return;
    float a0 = alpha[0], a1 = alpha[1], a2 = alpha[2], a3 = alpha[3];
    float m  = fmaxf(fmaxf(a0, a1), fmaxf(a2, a3));
    float w0 = expf(a0 - m), w1 = expf(a1 - m), w2 = expf(a2 - m), w3 = expf(a3 - m);
    float inv = 1.f / (w0 + w1 + w2 + w3);
    int stride = B * NQ;
    float y = w0 * g_branch[idx]
            + w1 * g_branch[stride + idx]
            + w2 * g_branch[2 * stride + idx]
            + w3 * g_branch[3 * stride + idx];
    out[idx] = y * inv;
}

extern "C" void kernel_launch(void* const* d_in, const int* in_sizes, int n_in,
                              void* d_out, int out_size)
{
    const float* features = (const float*)d_in[0];   // (B, 12)
    const float* theta    = (const float*)d_in[1];   // (4, 12, 3)
    const float* alpha    = (const float*)d_in[2];   // (4,)
    float* out = (float*)d_out;                      // (B, 12)

    int B = in_sizes[0] / NQ;
    if (B > MAXB) B = MAXB;

    const int SMEM_DYN = 4096 * (int)sizeof(ulonglong2);   // 64 KB double buffer
    cudaFuncSetAttribute(vqc_reg_kernel,
                         cudaFuncAttributeMaxDynamicSharedMemorySize, SMEM_DYN);

    prep_var_kernel<<<1, 64>>>(theta);            // writes g_vry, g_alpha, g_gamma
    prep_diag_kernel<<<24, 256>>>();              // reads g_alpha/g_gamma (same stream)
    int nenc = NENC * B * NQ;
    prep_enc_kernel<<<(nenc + 255) / 256, 256>>>(features, B);  // reads g_gamma

    dim3 grid(B, NENC);
    vqc_reg_kernel<<<grid, NT, SMEM_DYN>>>(B);

    int n = B * NQ;
    reduce_kernel<<<(n + 255) / 256, 256>>>(alpha, out, B);
}

// round 12
// speedup vs baseline: 5.4595x; 1.1851x over previous
#include <cuda_runtime.h>

#define NQ      12
#define NT      256
#define NWARP   8
#define LAYERS  4
#define NENC    4
#define MAXB    1024

typedef unsigned long long u64;

// ---------------- static device scratch (no allocations) ----------------
__device__ float g_branch[NENC * MAXB * NQ];
// real-Y gate coefficients (built by prep, mirrored into __constant__):
// per (l,q) 4 u64. q<11: [ (c,c), (s,s), 0, 0 ].
// q=11 (amp bit 0): [ dA=(c,c), oA=(-s,s), dB=(s,-s), oB=(c,c) ].
__device__ u64   g_vry[LAYERS * NQ * 4];
__constant__ u64 c_vry[LAYERS * NQ * 4];
// ZYZ diagonal angles per (l,q)
__device__ float g_alpha[LAYERS * NQ];
__device__ float g_gamma[LAYERS * NQ];
// boundary diagonals (theta-only, shared by all CTAs), LAYOUT-B indexing:
// slot = (j<<8)|(w<<5)|lane  ->  amp pair xp = (j<<8)|(lane<<3)|w
__device__ ulonglong2 g_diag[3 * 2048];
// encoding columns (gamma_1 folded): (c0.x, c0.y, c1.x, c1.y)
__device__ float4 g_em[NENC * MAXB * NQ];

// ---------------- scalar complex helpers (prep + encoding) ----------------
__device__ __forceinline__ float2 cmul(float2 a, float2 b) {
    return make_float2(fmaf(a.x, b.x, -a.y * b.y), fmaf(a.x, b.y, a.y * b.x));
}
__device__ __forceinline__ float2 cadd(float2 a, float2 b) {
    return make_float2(a.x + b.x, a.y + b.y);
}
struct M2 { float2 m00, m01, m10, m11; };
__device__ __forceinline__ M2 mmul(const M2& A, const M2& B) {
    M2 C;
    C.m00 = cadd(cmul(A.m00, B.m00), cmul(A.m01, B.m10));
    C.m01 = cadd(cmul(A.m00, B.m01), cmul(A.m01, B.m11));
    C.m10 = cadd(cmul(A.m10, B.m00), cmul(A.m11, B.m10));
    C.m11 = cadd(cmul(A.m10, B.m01), cmul(A.m11, B.m11));
    return C;
}
__device__ __forceinline__ M2 rx_m(float t) {
    float s, c; sincosf(0.5f * t, &s, &c);
    M2 M; M.m00 = {c, 0.f}; M.m01 = {0.f, -s}; M.m10 = {0.f, -s}; M.m11 = {c, 0.f};
    return M;
}
__device__ __forceinline__ M2 ry_m(float t) {
    float s, c; sincosf(0.5f * t, &s, &c);
    M2 M; M.m00 = {c, 0.f}; M.m01 = {-s, 0.f}; M.m10 = {s, 0.f}; M.m11 = {c, 0.f};
    return M;
}
__device__ __forceinline__ M2 rz_m(float t) {
    float s, c; sincosf(0.5f * t, &s, &c);
    M2 M; M.m00 = {c, -s}; M.m01 = {0.f, 0.f}; M.m10 = {0.f, 0.f}; M.m11 = {c, s};
    return M;
}

// ---------------- packed f32x2 primitives ----------------
__device__ __forceinline__ u64 pk2(float x, float y) {
    u64 r; asm("mov.b64 %0, {%1, %2};" : "=l"(r) : "f"(x), "f"(y)); return r;
}
__device__ __forceinline__ void upk2(u64 v, float& x, float& y) {
    asm("mov.b64 {%0, %1}, %2;" : "=f"(x), "=f"(y) : "l"(v));
}
__device__ __forceinline__ u64 pswap(u64 v) {
    float x, y; upk2(v, x, y); return pk2(y, x);
}
__device__ __forceinline__ u64 pmul(u64 a, u64 b) {
    u64 r; asm("mul.rn.f32x2 %0, %1, %2;" : "=l"(r) : "l"(a), "l"(b)); return r;
}
__device__ __forceinline__ u64 pfma(u64 a, u64 b, u64 c) {
    u64 r; asm("fma.rn.f32x2 %0, %1, %2, %3;" : "=l"(r) : "l"(a), "l"(b), "l"(c)); return r;
}
__device__ __forceinline__ u64 shfl64(u64 v, int m) {
    float x, y; upk2(v, x, y);
    x = __shfl_xor_sync(0xffffffffu, x, m);
    y = __shfl_xor_sync(0xffffffffu, y, m);
    return pk2(x, y);
}

#define SIGNMASK 0x8000000080000000ULL

// ---------------- prep kernels ----------------
__global__ void prep_var_kernel(const float* __restrict__ theta) {
    int idx = blockIdx.x * blockDim.x + threadIdx.x;        // l*NQ + q
    if (idx >= LAYERS * NQ) return;
    int q = idx % NQ;
    const float* th = theta + idx * 3;
    M2 M = mmul(rz_m(th[2]), mmul(ry_m(th[1]), rx_m(th[0])));
    float c = sqrtf(fmaf(M.m00.x, M.m00.x, M.m00.y * M.m00.y));
    float s = sqrtf(fmaf(M.m10.x, M.m10.x, M.m10.y * M.m10.y));
    float p00 = atan2f(M.m00.y, M.m00.x);
    float p10 = atan2f(M.m10.y, M.m10.x);
    g_alpha[idx] = p10 - p00;
    g_gamma[idx] = -p10 - p00;
    u64* dst = g_vry + idx * 4;
    if (q < 11) {
        dst[0] = pk2(c, c); dst[1] = pk2(s, s);
        dst[2] = 0; dst[3] = 0;
    } else {
        dst[0] = pk2(c, c);   dst[1] = pk2(-s, s);    // set A (even j)
        dst[2] = pk2(s, -s);  dst[3] = pk2(c, c);     // set B (odd j, row-swapped)
    }
}

// boundary diagonal l, LAYOUT-B slot indexing:
//   slot idx = (j<<8)|(w<<5)|lane; amp pair xp = (j<<8)|(lane<<3)|w
//   delta_l(x) = d_alpha[l](Ce x) * d_gamma[l+1](Co x)
__global__ void prep_diag_kernel() {
    int idx = blockIdx.x * blockDim.x + threadIdx.x;
    if (idx >= 3 * 2048) return;
    int l    = idx >> 11;
    int slot = idx & 2047;
    int j    = (slot >> 8) & 7;
    int w    = (slot >> 5) & 7;
    int lane = slot & 31;
    int xp   = (j << 8) | (lane << 3) | w;      // layout B
    const float* al = g_alpha + l * NQ;
    const float* gm = g_gamma + (l + 1) * NQ;
    float rr[2], ii[2];
    #pragma unroll
    for (int h = 0; h < 2; h++) {
        int x  = (xp << 1) | h;
        int ye = x ^ ((x >> 1) & 0x555);
        int yo = x ^ ((x >> 1) & 0x2AA);
        float ang = 0.f;
        for (int q = 0; q < NQ; q++) {
            int p = 11 - q;
            ang += ((ye >> p) & 1) ? 0.5f * al[q] : -0.5f * al[q];
            ang += ((yo >> p) & 1) ? 0.5f * gm[q] : -0.5f * gm[q];
        }
        float sn, cs; sincosf(ang, &sn, &cs);
        rr[h] = cs; ii[h] = sn;
    }
    g_diag[idx] = make_ulonglong2(pk2(rr[0], rr[1]), pk2(ii[0], ii[1]));
}

__global__ void prep_enc_kernel(const float* __restrict__ features, int B) {
    int idx = blockIdx.x * blockDim.x + threadIdx.x;        // e*B*NQ + b*NQ + q
    if (idx >= NENC * B * NQ) return;
    int q = idx % NQ;
    int b = (idx / NQ) % B;
    int e = idx / (B * NQ);
    float f = features[b * NQ + q];
    M2 R = (e & 1) ? ry_m(f) : rx_m(f);
    if (e >= 2) {
        const float r = 0.7071067811865476f;
        M2 H; H.m00 = {r, 0.f}; H.m01 = {r, 0.f}; H.m10 = {r, 0.f}; H.m11 = {-r, 0.f};
        R = mmul(R, H);
    }
    float g = g_gamma[q];          // fold layer-1 gamma diagonal
    float sg, cg; sincosf(0.5f * g, &sg, &cg);
    float2 c0 = cmul(make_float2(R.m00.x, R.m00.y), make_float2(cg, -sg));
    float2 c1 = cmul(make_float2(R.m10.x, R.m10.y), make_float2(cg, sg));
    g_em[idx] = make_float4(c0.x, c0.y, c1.x, c1.y);
}

// ---------------- real-rotation gate primitives ----------------
// Layout A: amp = (w<<9)|(lane<<4)|(j<<1)|h.
// Layout B: amp = (j<<9)|(lane<<4)|(w<<1)|h  (after transpose3).
// sr[j]/si[j] hold (h=0, h=1) packed per f32x2.

__device__ __forceinline__ void ldRG(const u64* __restrict__ p, u64& c, u64& s) {
    c = p[0]; s = p[1];
}

template<int JB, int PREJ, int POSTJ>
__device__ __forceinline__ void gate_jr(u64 sr[8], u64 si[8],
                                        u64 P00, u64 P01, u64 P10, u64 P11) {
    #pragma unroll
    for (int j = 0; j < 8; j++) {
        if (!(j & JB)) {
            const int j1 = j | JB;
            const bool pre  = (PREJ != 0) && ((j & PREJ) != 0);
            const bool post = (POSTJ != 0) && ((j & POSTJ) != 0);
            const int ja = pre ? j1 : j, jb = pre ? j : j1;
            u64 Ar = sr[ja], Ai = si[ja], Br = sr[jb], Bi = si[jb];
            u64 o0r = pfma(P01, Br, pmul(P00, Ar));
            u64 o0i = pfma(P01, Bi, pmul(P00, Ai));
            u64 o1r = pfma(P11, Br, pmul(P10, Ar));
            u64 o1i = pfma(P11, Bi, pmul(P10, Ai));
            sr[post ? j1 : j] = o0r; si[post ? j1 : j] = o0i;
            sr[post ? j : j1] = o1r; si[post ? j : j1] = o1i;
        }
    }
}

__device__ __forceinline__ void gate_laner(u64 sr[8], u64 si[8], u64 c, u64 s,
                                           int mask, int lane, bool cswap, bool rxor) {
    u64 ns = s ^ SIGNMASK;
    const bool hi   = (lane & mask) != 0;
    const bool row  = hi ^ rxor;
    const bool scol = hi ^ cswap;
    u64 sgn = row ? s : ns;
    u64 P = (row == scol) ? c : sgn;
    u64 Q = (row == scol) ? sgn : c;
    #pragma unroll
    for (int j = 0; j < 8; j++) {
        u64 orr = shfl64(sr[j], mask);
        u64 oii = shfl64(si[j], mask);
        sr[j] = pfma(Q, orr, pmul(P, sr[j]));
        si[j] = pfma(Q, oii, pmul(P, si[j]));
    }
}

// b8 lane gate in LAYOUT B: mask 16, post CNOT row-swap controlled by b9 = j bit 0.
__device__ __forceinline__ void gate_laner_b8(u64 sr[8], u64 si[8], u64 c, u64 s, int lane) {
    u64 ns = s ^ SIGNMASK;
    const bool hi = (lane & 16) != 0;
    u64 Qe = hi ? s : ns;      // even j: P=c, Q=M[hi][hi^1]
    u64 Po = hi ? ns : s;      // odd j:  P=M[hi^1][hi], Q=c
    #pragma unroll
    for (int j = 0; j < 8; j++) {
        u64 orr = shfl64(sr[j], 16);
        u64 oii = shfl64(si[j], 16);
        if (j & 1) {
            sr[j] = pfma(c, orr, pmul(Po, sr[j]));
            si[j] = pfma(c, oii, pmul(Po, si[j]));
        } else {
            sr[j] = pfma(Qe, orr, pmul(c, sr[j]));
            si[j] = pfma(Qe, oii, pmul(c, si[j]));
        }
    }
}

// wire-11 gate on amp bit 0 (within-u64); post CNOT(ctrl=b1) fused via set B
__device__ __forceinline__ void gate_hr(u64 sr[8], u64 si[8], const u64* __restrict__ p) {
    u64 dA = p[0], oA = p[1], dB = p[2], oB = p[3];
    #pragma unroll
    for (int j = 0; j < 8; j++) {
        u64 d = (j & 1) ? dB : dA;
        u64 o = (j & 1) ? oB : oA;
        sr[j] = pfma(o, pswap(sr[j]), pmul(d, sr[j]));
        si[j] = pfma(o, pswap(si[j]), pmul(d, si[j]));
    }
}

// boundary diagonal: per-amp complex multiply (state in LAYOUT B)
__device__ __forceinline__ void apply_diag(u64 sr[8], u64 si[8],
                                           const ulonglong2* __restrict__ tab, int tid) {
    #pragma unroll
    for (int j = 0; j < 8; j++) {
        ulonglong2 v = tab[(j << 8) | tid];
        u64 dr = v.x, di = v.y, dni = di ^ SIGNMASK;
        u64 nr = pfma(dni, si[j], pmul(dr, sr[j]));
        u64 ni = pfma(dr,  si[j], pmul(di, sr[j]));
        sr[j] = nr; si[j] = ni;
    }
}

// ---------------- layout transpose: amp bits 1-3 <-> 9-11 ----------------
template<bool HIGHSTORE>
__device__ __forceinline__ void transpose3(u64 sr[8], u64 si[8],
                                           ulonglong2* __restrict__ buf,
                                           int lane, int w) {
    #pragma unroll
    for (int j = 0; j < 8; j++) {
        int u = HIGHSTORE ? ((j << 8) | (lane << 3) | w)
                          : ((w << 8) | (lane << 3) | j);
        buf[u ^ (lane & 7)] = make_ulonglong2(sr[j], si[j]);
    }
    __syncthreads();
    #pragma unroll
    for (int j = 0; j < 8; j++) {
        int u = HIGHSTORE ? ((w << 8) | (lane << 3) | j)
                          : ((j << 8) | (lane << 3) | w);
        ulonglong2 v = buf[u ^ (lane & 7)];
        sr[j] = v.x; si[j] = v.y;
    }
}

// Sweep: [A-phase] T(A->B) [B-phase (+diag)] T(B->A unless LAST).
// A-phase (layout A): b1,b3 (reg, pre), b7,b5 (lane, pre), b2,b0 (reg, post),
// b6,b4 (lane, post). B-phase (layout B): b11, b9(pre), b10(post) reg;
// b8 lane with per-j post row swap (ctrl b9 = j bit0). All CNOT-absorption
// precedence edges verified: pre gates before their ctrl-bit gates, post
// gates after their ctrl-bit gates, absorbed CNOTs disjoint from interposers.
template<bool PRE, bool LAST>
__device__ __forceinline__ void vsweep2(const u64* __restrict__ m,
                                        const ulonglong2* __restrict__ dtab,
                                        u64 sr[8], u64 si[8],
                                        ulonglong2* bufAB, ulonglong2* bufBA,
                                        int lane, int w, int tid) {
    u64 c, s, ns;
    // ---- phase A ----
    ldRG(m + 10*4, c, s); ns = s ^ SIGNMASK;                        // b1 (wire 10), pre c=b2
    if (PRE) gate_jr<1, 2, 0>(sr, si, c, ns, s, c);
    else     gate_jr<1, 0, 0>(sr, si, c, ns, s, c);
    ldRG(m + 8*4, c, s); ns = s ^ SIGNMASK;                         // b3 (wire 8), pre c=b4 (lane bit0)
    {
        bool cs3 = PRE && (lane & 1);
        u64 q00 = cs3 ? ns : c, q01 = cs3 ? c : ns;
        u64 q10 = cs3 ? c : s,  q11v = cs3 ? s : c;
        gate_jr<4, 0, 0>(sr, si, q00, q01, q10, q11v);
    }
    ldRG(m + 4*4, c, s);                                            // b7 (wire 4), pre c=b8
    gate_laner(sr, si, c, s, 8, lane, PRE && (lane & 16), false);
    ldRG(m + 6*4, c, s);                                            // b5 (wire 6), pre c=b6
    gate_laner(sr, si, c, s, 2, lane, PRE && (lane & 4), false);
    ldRG(m + 9*4, c, s); ns = s ^ SIGNMASK;                         // b2 (wire 9), post c=b3
    gate_jr<2, 0, 4>(sr, si, c, ns, s, c);
    gate_hr(sr, si, m + 11*4);                                      // b0 (wire 11), post c=b1
    ldRG(m + 5*4, c, s);                                            // b6 (wire 5), post c=b7
    gate_laner(sr, si, c, s, 4, lane, false, (lane & 8) != 0);
    ldRG(m + 7*4, c, s);                                            // b4 (wire 7), post c=b5
    gate_laner(sr, si, c, s, 1, lane, false, (lane & 2) != 0);
    // ---- T(A->B) ----
    transpose3<false>(sr, si, bufAB, lane, w);
    // ---- phase B ----
    ldRG(m + 0*4, c, s); ns = s ^ SIGNMASK;                         // b11 (wire 0)
    gate_jr<4, 0, 0>(sr, si, c, ns, s, c);
    ldRG(m + 2*4, c, s); ns = s ^ SIGNMASK;                         // b9 (wire 2), pre c=b10 (j bit1)
    if (PRE) gate_jr<1, 2, 0>(sr, si, c, ns, s, c);
    else     gate_jr<1, 0, 0>(sr, si, c, ns, s, c);
    ldRG(m + 1*4, c, s); ns = s ^ SIGNMASK;                         // b10 (wire 1), post c=b11 (j bit2)
    gate_jr<2, 0, 4>(sr, si, c, ns, s, c);
    ldRG(m + 3*4, c, s);                                            // b8 (wire 3), post c=b9 (j bit0)
    gate_laner_b8(sr, si, c, s, lane);
    if (!LAST) {
        apply_diag(sr, si, dtab, tid);
        transpose3<true>(sr, si, bufBA, lane, w);
    }
}

// ---------------- main kernel ----------------
__global__ __launch_bounds__(NT, 2)
void vqc_reg_kernel(int B)
{
    extern __shared__ ulonglong2 dynbuf[];   // [0..2047] bufAB, [2048..4095] bufBA
    __shared__ float red[NWARP * NQ];
    ulonglong2* bufAB = dynbuf;
    ulonglong2* bufBA = dynbuf + 2048;

    const int b    = blockIdx.x;
    const int e    = blockIdx.y;
    const int tid  = threadIdx.x;
    const int lane = tid & 31;
    const int w    = tid >> 5;

    // ---- encoding: direct product-state construction (layout A) ----
    const float4* col = g_em + (e * B + b) * NQ;
    float2 ph;
    {
        float4 c0 = col[0];
        ph = ((tid >> 7) & 1) ? make_float2(c0.z, c0.w) : make_float2(c0.x, c0.y);
        #pragma unroll
        for (int q = 1; q < 8; q++) {
            float4 cq = col[q];
            float2 v = ((tid >> (7 - q)) & 1) ? make_float2(cq.z, cq.w)
                                              : make_float2(cq.x, cq.y);
            ph = cmul(ph, v);
        }
    }
    u64 sr[8], si[8];
    {
        float4 c8 = col[8], c9 = col[9], c10 = col[10], c11 = col[11];
        float2 t2[2], t4[4], t8[8];
        t2[0] = cmul(ph, make_float2(c8.x, c8.y));
        t2[1] = cmul(ph, make_float2(c8.z, c8.w));
        #pragma unroll
        for (int i = 0; i < 2; i++) {
            t4[i*2+0] = cmul(t2[i], make_float2(c9.x, c9.y));
            t4[i*2+1] = cmul(t2[i], make_float2(c9.z, c9.w));
        }
        #pragma unroll
        for (int i = 0; i < 4; i++) {
            t8[i*2+0] = cmul(t4[i], make_float2(c10.x, c10.y));
            t8[i*2+1] = cmul(t4[i], make_float2(c10.z, c10.w));
        }
        #pragma unroll
        for (int j = 0; j < 8; j++) {
            float2 a  = cmul(t8[j], make_float2(c11.x, c11.y));   // h = 0
            float2 bm = cmul(t8[j], make_float2(c11.z, c11.w));   // h = 1
            sr[j] = pk2(a.x, bm.x);
            si[j] = pk2(a.y, bm.y);
        }
    }

    // ---- variational layers ----
    vsweep2<false, false>(c_vry + 0*48, g_diag + 0*2048, sr, si, bufAB, bufBA, lane, w, tid);
    vsweep2<true,  false>(c_vry + 1*48, g_diag + 1*2048, sr, si, bufAB, bufBA, lane, w, tid);
    vsweep2<true,  false>(c_vry + 2*48, g_diag + 2*2048, sr, si, bufAB, bufBA, lane, w, tid);
    vsweep2<true,  true >(c_vry + 3*48, (const ulonglong2*)0, sr, si, bufAB, bufBA, lane, w, tid);
    // state ends in LAYOUT B: amp = (j<<9)|(lane<<4)|(w<<1)|h
    // alpha_4 drops at measurement; layer-4 odd ladder -> epilogue sign
    // permutation: b9^=b10, b7^=b8, b5^=b6, b3^=b4, b1^=b2

    // ---- <Z_q>, layout-B bit mapping ----
    // k = 2j+h: k bit0 = b0, k bits 1-3 = b9,b10,b11. tid bits 0-4 = b4..b8,
    // tid bits 5-7 = b1,b2,b3.
    float t[16], tot = 0.f;
    #pragma unroll
    for (int j = 0; j < 8; j++) {
        u64 p2 = pfma(si[j], si[j], pmul(sr[j], sr[j]));
        float p0, p1; upk2(p2, p0, p1);
        t[2*j] = p0; t[2*j+1] = p1;
        tot += p0 + p1;
    }
    float aq0 = 0.f, aq1 = 0.f, aq2 = 0.f, aq11 = 0.f;
    #pragma unroll
    for (int k = 0; k < 16; k++) {
        aq0  += (k & 8) ? -t[k] : t[k];                      // b11   (k bit 3)
        aq1  += (k & 4) ? -t[k] : t[k];                      // b10   (k bit 2)
        aq2  += (((k >> 1) ^ (k >> 2)) & 1) ? -t[k] : t[k];  // b9^b10
        aq11 += (k & 1) ? -t[k] : t[k];                      // b0    (k bit 0)
    }
    float ez[NQ];
    ez[0]  = aq0;
    ez[1]  = aq1;
    ez[2]  = aq2;
    ez[3]  = ((tid >> 4) & 1)                   ? -tot : tot;  // b8
    ez[4]  = (((tid >> 3) ^ (tid >> 4)) & 1)    ? -tot : tot;  // b7^b8
    ez[5]  = ((tid >> 2) & 1)                   ? -tot : tot;  // b6
    ez[6]  = (((tid >> 1) ^ (tid >> 2)) & 1)    ? -tot : tot;  // b5^b6
    ez[7]  = (tid & 1)                          ? -tot : tot;  // b4
    ez[8]  = (((tid >> 7) ^ tid) & 1)           ? -tot : tot;  // b3^b4
    ez[9]  = ((tid >> 6) & 1)                   ? -tot : tot;  // b2
    ez[10] = (((tid >> 5) ^ (tid >> 6)) & 1)    ? -tot : tot;  // b1^b2
    ez[11] = aq11;

    #pragma unroll
    for (int q = 0; q < NQ; q++)
        #pragma unroll
        for (int o = 16; o > 0; o >>= 1)
            ez[q] += __shfl_xor_sync(0xffffffffu, ez[q], o);

    if (lane == 0) {
        #pragma unroll
        for (int q = 0; q < NQ; q++) red[w * NQ + q] = ez[q];
    }
    __syncthreads();
    if (tid < NQ) {
        float acc = 0.f;
        #pragma unroll
        for (int j = 0; j < NWARP; j++) acc += red[j * NQ + tid];
        g_branch[(e * B + b) * NQ + tid] = acc;
    }
}

// ---------------- softmax(alpha)-weighted branch mix ----------------
__global__ void reduce_kernel(const float* __restrict__ alpha,
                              float* __restrict__ out, int B)
{
    int idx = blockIdx.x * blockDim.x + threadIdx.x;
    if (idx >= B * NQ) return;
    float a0 = alpha[0], a1 = alpha[1], a2 = alpha[2], a3 = alpha[3];
    float m  = fmaxf(fmaxf(a0, a1), fmaxf(a2, a3));
    float w0 = expf(a0 - m), w1 = expf(a1 - m), w2 = expf(a2 - m), w3 = expf(a3 - m);
    float inv = 1.f / (w0 + w1 + w2 + w3);
    int stride = B * NQ;
    float y = w0 * g_branch[idx]
            + w1 * g_branch[stride + idx]
            + w2 * g_branch[2 * stride + idx]
            + w3 * g_branch[3 * stride + idx];
    out[idx] = y * inv;
}

extern "C" void kernel_launch(void* const* d_in, const int* in_sizes, int n_in,
                              void* d_out, int out_size)
{
    const float* features = (const float*)d_in[0];   // (B, 12)
    const float* theta    = (const float*)d_in[1];   // (4, 12, 3)
    const float* alpha    = (const float*)d_in[2];   // (4,)
    float* out = (float*)d_out;                      // (B, 12)

    int B = in_sizes[0] / NQ;
    if (B > MAXB) B = MAXB;

    const int SMEM_DYN = 4096 * (int)sizeof(ulonglong2);   // 64 KB double buffer
    cudaFuncSetAttribute(vqc_reg_kernel,
                         cudaFuncAttributeMaxDynamicSharedMemorySize, SMEM_DYN);

    prep_var_kernel<<<1, 64>>>(theta);            // writes g_vry, g_alpha, g_gamma

    // mirror gate coefficients into __constant__ (D2D async copy, graph-legal)
    void* vry_dev = 0;
    cudaGetSymbolAddress(&vry_dev, g_vry);
    cudaMemcpyToSymbolAsync(c_vry, vry_dev, sizeof(u64) * LAYERS * NQ * 4, 0,
                            cudaMemcpyDeviceToDevice, 0);

    prep_diag_kernel<<<24, 256>>>();              // reads g_alpha/g_gamma
    int nenc = NENC * B * NQ;
    prep_enc_kernel<<<(nenc + 255) / 256, 256>>>(features, B);  // reads g_gamma

    dim3 grid(B, NENC);
    vqc_reg_kernel<<<grid, NT, SMEM_DYN>>>(B);

    int n = B * NQ;
    reduce_kernel<<<(n + 255) / 256, 256>>>(alpha, out, B);
}